// round 1
// baseline (speedup 1.0000x reference)
#include <cuda_runtime.h>
#include <math.h>

// Problem constants
#define CIN   1536
#define COUT  3072
#define TT    16
#define HF    14
#define WF    14
#define NOUT  7          // roi output grid
#define NCOLS (TT * NOUT * NOUT)   // 784 GEMM columns
#define PLANE (HF * WF)            // 196

// Scratch (device globals — no allocation allowed)
__device__ float g_Bmat[CIN * NCOLS];    // packed subsampled y: [k][n]
__device__ float g_G[COUT * NCOLS];      // gelu(bn(conv)) result: [o][n]

// ---------------------------------------------------------------------------
// Kernel 1: pack y[:, :, t, ::2, ::2] into contiguous (CIN x NCOLS)
// ---------------------------------------------------------------------------
__global__ void pack_kernel(const float* __restrict__ y) {
    int idx = blockIdx.x * blockDim.x + threadIdx.x;
    if (idx >= CIN * NCOLS) return;
    int k = idx / NCOLS;
    int n = idx - k * NCOLS;
    int t = n / (NOUT * NOUT);
    int r = n - t * (NOUT * NOUT);
    int oy = r / NOUT;
    int ox = r - oy * NOUT;
    g_Bmat[idx] = y[((k * TT + t) * HF + 2 * oy) * WF + 2 * ox];
}

// ---------------------------------------------------------------------------
// Kernel 2: fp32 GEMM (COUT x CIN) * (CIN x NCOLS) + bias + BN + exact GELU
// 64x64 block tile, BK=16, 4x4 thread tile, 256 threads
// ---------------------------------------------------------------------------
#define BM 64
#define BN 64
#define BK 16
#define TM 4
#define TN 4

__global__ void __launch_bounds__(256) gemm_bn_gelu_kernel(
    const float* __restrict__ W,      // (COUT, CIN) row-major
    const float* __restrict__ bias,
    const float* __restrict__ gamma,
    const float* __restrict__ beta,
    const float* __restrict__ rmean,
    const float* __restrict__ rvar)
{
    __shared__ float As[BK][BM];   // transposed A tile
    __shared__ float Bs[BK][BN];

    const int bm = blockIdx.y * BM;
    const int bn = blockIdx.x * BN;
    const int tid = threadIdx.x;

    const int tx = tid & 15;       // n-direction (0..15)
    const int ty = tid >> 4;       // m-direction (0..15)

    // A tile load mapping: 64 rows x 16 k, float4 along k
    const int arow = tid >> 2;           // 0..63
    const int acol = (tid & 3) * 4;      // 0,4,8,12
    // B tile load mapping: 16 k-rows x 64 n, float4 along n
    const int brow = tid >> 4;           // 0..15
    const int bcol = (tid & 15) * 4;     // 0..60
    const int bcolg = bn + bcol;

    float acc[TM][TN];
#pragma unroll
    for (int i = 0; i < TM; i++)
#pragma unroll
        for (int j = 0; j < TN; j++) acc[i][j] = 0.0f;

    const float* Wp = W + (size_t)(bm + arow) * CIN + acol;

    for (int k0 = 0; k0 < CIN; k0 += BK) {
        float4 av = *(const float4*)(Wp + k0);
        As[acol + 0][arow] = av.x;
        As[acol + 1][arow] = av.y;
        As[acol + 2][arow] = av.z;
        As[acol + 3][arow] = av.w;

        float4 bv = make_float4(0.f, 0.f, 0.f, 0.f);
        if (bcolg < NCOLS)
            bv = *(const float4*)(g_Bmat + (size_t)(k0 + brow) * NCOLS + bcolg);
        *(float4*)&Bs[brow][bcol] = bv;

        __syncthreads();

#pragma unroll
        for (int k = 0; k < BK; k++) {
            float4 a = *(const float4*)&As[k][ty * 4];
            float4 b = *(const float4*)&Bs[k][tx * 4];
            float am[4] = {a.x, a.y, a.z, a.w};
            float bb[4] = {b.x, b.y, b.z, b.w};
#pragma unroll
            for (int i = 0; i < TM; i++)
#pragma unroll
                for (int j = 0; j < TN; j++)
                    acc[i][j] = fmaf(am[i], bb[j], acc[i][j]);
        }
        __syncthreads();
    }

    // Epilogue: bias + BN + exact GELU (x * Phi(x))
#pragma unroll
    for (int i = 0; i < TM; i++) {
        int o = bm + ty * 4 + i;
        float inv = gamma[o] * rsqrtf(rvar[o] + 1e-6f);
        float b0 = bias[o];
        float mu = rmean[o];
        float be = beta[o];
#pragma unroll
        for (int j = 0; j < TN; j++) {
            int n = bn + tx * 4 + j;
            if (n < NCOLS) {
                float v = acc[i][j] + b0;
                v = (v - mu) * inv + be;
                v = v * normcdff(v);
                g_G[(size_t)o * NCOLS + n] = v;
            }
        }
    }
}

// ---------------------------------------------------------------------------
// Kernel 3: ROI-align + windowed place + residual add.
// One block per (c, t) plane. 224 threads (196 active).
// ---------------------------------------------------------------------------
__device__ __forceinline__ float bilin(const float* tile, float py, float px) {
    if (py < -1.0f || py > (float)HF || px < -1.0f || px > (float)WF) return 0.0f;
    float yc = fminf(fmaxf(py, 0.0f), (float)(HF - 1));
    float xc = fminf(fmaxf(px, 0.0f), (float)(WF - 1));
    int y0 = (int)floorf(yc);
    int x0 = (int)floorf(xc);
    int y1i = min(y0 + 1, HF - 1);
    int x1i = min(x0 + 1, WF - 1);
    float ly = yc - (float)y0;
    float lx = xc - (float)x0;
    float v00 = tile[y0 * WF + x0];
    float v01 = tile[y0 * WF + x1i];
    float v10 = tile[y1i * WF + x0];
    float v11 = tile[y1i * WF + x1i];
    return (1.f - ly) * ((1.f - lx) * v00 + lx * v01)
         + ly * ((1.f - lx) * v10 + lx * v11);
}

__global__ void __launch_bounds__(224) roi_place_kernel(
    const float* __restrict__ x_t,
    const float* __restrict__ rois,
    float* __restrict__ out)
{
    __shared__ float tile[PLANE];
    const int c = blockIdx.x;
    const int t = blockIdx.y;
    const int tid = threadIdx.x;

    const float* plane = x_t + (size_t)(c * TT + t) * PLANE;
    if (tid < PLANE) tile[tid] = plane[tid];

    // ROI constants for this t (computed redundantly per thread; cheap)
    const float SCALE = 1.0f / 16.0f;
    float bx1 = rois[t * 4 + 0] * SCALE;
    float by1 = rois[t * 4 + 1] * SCALE;
    float bx2 = rois[t * 4 + 2] * SCALE;
    float by2 = rois[t * 4 + 3] * SCALE;
    float rw = fmaxf(bx2 - bx1, 1.0f);
    float rh = fmaxf(by2 - by1, 1.0f);
    float bw = rw / (float)NOUT;
    float bh = rh / (float)NOUT;

    int sxi = (int)floorf(bx1);
    int syi = (int)floorf(by1);
    int exi = (int)ceilf(bx2);
    int eyi = (int)ceilf(by2);
    int ml = (sxi + NOUT < HF) ? sxi : (exi - NOUT);
    int mt = (syi + NOUT < HF) ? syi : (eyi - NOUT);

    __syncthreads();

    if (tid < PLANE) {
        int h = tid / WF;
        int w = tid - h * WF;
        float xval = tile[tid];
        float val = 0.0f;
        int oy = h - mt;
        int ox = w - ml;
        if (oy >= 0 && oy < NOUT && ox >= 0 && ox < NOUT) {
            float mr = 0.0f;
#pragma unroll
            for (int s = 0; s < 2; s++) {
                float py = by1 + ((float)oy + ((float)s + 0.5f) * 0.5f) * bh;
#pragma unroll
                for (int r = 0; r < 2; r++) {
                    float px = bx1 + ((float)ox + ((float)r + 0.5f) * 0.5f) * bw;
                    mr += bilin(tile, py, px);
                }
            }
            mr *= 0.25f;
            float g = g_G[(size_t)c * NCOLS + t * (NOUT * NOUT) + oy * NOUT + ox];
            val = g * mr;
        }
        out[(size_t)(c * TT + t) * PLANE + tid] = xval + val;
    }
}

// ---------------------------------------------------------------------------
// Launch
// ---------------------------------------------------------------------------
extern "C" void kernel_launch(void* const* d_in, const int* in_sizes, int n_in,
                              void* d_out, int out_size) {
    const float* y      = (const float*)d_in[0];
    const float* x_t    = (const float*)d_in[1];
    const float* rois   = (const float*)d_in[2];
    const float* conv_w = (const float*)d_in[3];
    const float* conv_b = (const float*)d_in[4];
    const float* gamma  = (const float*)d_in[5];
    const float* beta   = (const float*)d_in[6];
    const float* rmean  = (const float*)d_in[7];
    const float* rvar   = (const float*)d_in[8];
    float* out = (float*)d_out;

    // 1) pack subsampled y
    {
        int n = CIN * NCOLS;
        pack_kernel<<<(n + 255) / 256, 256>>>(y);
    }
    // 2) GEMM + BN + GELU
    {
        dim3 grid((NCOLS + BN - 1) / BN, COUT / BM);  // (13, 48)
        gemm_bn_gelu_kernel<<<grid, 256>>>(conv_w, conv_b, gamma, beta, rmean, rvar);
    }
    // 3) ROI-align + place + residual
    {
        dim3 grid(COUT, TT);
        roi_place_kernel<<<grid, 224>>>(x_t, rois, out);
    }
}

// round 2
// speedup vs baseline: 1.6412x; 1.6412x over previous
#include <cuda_runtime.h>
#include <cuda_bf16.h>
#include <math.h>

// Problem constants
#define CIN   1536
#define COUT  3072
#define TT    16
#define HF    14
#define WF    14
#define NOUT  7
#define NCOLS (TT * NOUT * NOUT)   // 784
#define NPAD  832                  // 13 * 64
#define PLANE (HF * WF)            // 196

// ---------------------------------------------------------------------------
// Device scratch (no allocation allowed)
// ---------------------------------------------------------------------------
__device__ __align__(16) __nv_bfloat16 g_Wh[COUT * CIN];
__device__ __align__(16) __nv_bfloat16 g_Wl[COUT * CIN];
__device__ __align__(16) __nv_bfloat16 g_Bh[CIN * NPAD];
__device__ __align__(16) __nv_bfloat16 g_Bl[CIN * NPAD];
__device__ __align__(16) float g_G[COUT * NCOLS];

// ---------------------------------------------------------------------------
// Kernel 0: convert conv_w (fp32) -> bf16 hi/lo split
// ---------------------------------------------------------------------------
__global__ void convert_w_kernel(const float* __restrict__ W) {
    int i = blockIdx.x * blockDim.x + threadIdx.x;
    const int n4 = (COUT * CIN) / 4;
    if (i >= n4) return;
    float4 v = ((const float4*)W)[i];
    __nv_bfloat16 h0 = __float2bfloat16_rn(v.x);
    __nv_bfloat16 h1 = __float2bfloat16_rn(v.y);
    __nv_bfloat16 h2 = __float2bfloat16_rn(v.z);
    __nv_bfloat16 h3 = __float2bfloat16_rn(v.w);
    __nv_bfloat16 l0 = __float2bfloat16_rn(v.x - __bfloat162float(h0));
    __nv_bfloat16 l1 = __float2bfloat16_rn(v.y - __bfloat162float(h1));
    __nv_bfloat16 l2 = __float2bfloat16_rn(v.z - __bfloat162float(h2));
    __nv_bfloat16 l3 = __float2bfloat16_rn(v.w - __bfloat162float(h3));
    __nv_bfloat162* Wh2 = (__nv_bfloat162*)g_Wh;
    __nv_bfloat162* Wl2 = (__nv_bfloat162*)g_Wl;
    Wh2[i * 2 + 0] = __nv_bfloat162{h0, h1};
    Wh2[i * 2 + 1] = __nv_bfloat162{h2, h3};
    Wl2[i * 2 + 0] = __nv_bfloat162{l0, l1};
    Wl2[i * 2 + 1] = __nv_bfloat162{l2, l3};
}

// ---------------------------------------------------------------------------
// Kernel 1: pack y[:, :, t, ::2, ::2] -> bf16 hi/lo, k-major [CIN][NPAD]
// ---------------------------------------------------------------------------
__global__ void pack_kernel(const float* __restrict__ y) {
    int idx = blockIdx.x * blockDim.x + threadIdx.x;
    if (idx >= CIN * NPAD) return;
    int k = idx / NPAD;
    int n = idx - k * NPAD;
    float v = 0.0f;
    if (n < NCOLS) {
        int t = n / (NOUT * NOUT);
        int r = n - t * (NOUT * NOUT);
        int oy = r / NOUT;
        int ox = r - oy * NOUT;
        v = y[((k * TT + t) * HF + 2 * oy) * WF + 2 * ox];
    }
    __nv_bfloat16 h = __float2bfloat16_rn(v);
    g_Bh[idx] = h;
    g_Bl[idx] = __float2bfloat16_rn(v - __bfloat162float(h));
}

// ---------------------------------------------------------------------------
// Kernel 2: split-bf16 tensor-core GEMM (COUT x CIN)*(CIN x NPAD)
//           + bias + BN + exact GELU  ->  g_G (fp32, [COUT][NCOLS])
// Tiles: BM=128, BN=64, BK=32; 256 threads (8 warps, 4x2 warp grid, 32x32/warp)
// Double-buffered cp.async. 3 MMA products: hh + hl + lh.
// ---------------------------------------------------------------------------
#define BM 128
#define BN 64
#define BK 32
#define KSTEPS (CIN / BK)     // 48
#define ASTR 40               // padded k-stride for A tiles (bf16 units)
#define BSTR 72               // padded n-stride for B tiles (bf16 units)

// SMEM stage layout (bf16 element offsets)
#define AH_OFF 0
#define AL_OFF (BM * ASTR)                 // 5120
#define BH_OFF (2 * BM * ASTR)             // 10240
#define BL_OFF (BH_OFF + BK * BSTR)        // 12544
#define STAGE_ELEMS (BL_OFF + BK * BSTR)   // 14848
#define SMEM_BYTES (2 * STAGE_ELEMS * 2)   // 59392

__device__ __forceinline__ void cp16(void* smem, const void* gmem) {
    unsigned sa = (unsigned)__cvta_generic_to_shared(smem);
    asm volatile("cp.async.cg.shared.global [%0], [%1], 16;\n" :: "r"(sa), "l"(gmem));
}

#define MMA_BF16(c, a, b0, b1)                                              \
    asm volatile(                                                           \
        "mma.sync.aligned.m16n8k16.row.col.f32.bf16.bf16.f32 "              \
        "{%0,%1,%2,%3}, {%4,%5,%6,%7}, {%8,%9}, {%0,%1,%2,%3};\n"           \
        : "+f"(c[0]), "+f"(c[1]), "+f"(c[2]), "+f"(c[3])                    \
        : "r"(a[0]), "r"(a[1]), "r"(a[2]), "r"(a[3]), "r"(b0), "r"(b1))

extern __shared__ __nv_bfloat16 smem_buf[];

__global__ void __launch_bounds__(256) gemm_bn_gelu_kernel(
    const float* __restrict__ bias,
    const float* __restrict__ gamma,
    const float* __restrict__ beta,
    const float* __restrict__ rmean,
    const float* __restrict__ rvar)
{
    const int tid = threadIdx.x;
    const int bm = blockIdx.y * BM;
    const int bn = blockIdx.x * BN;

    const int lane = tid & 31;
    const int warp = tid >> 5;
    const int wm = warp >> 1;       // 0..3
    const int wn = warp & 1;        // 0..1
    const int frow = lane >> 2;     // 0..7
    const int fcolp = (lane & 3) * 2;

    float acc[2][4][4];
#pragma unroll
    for (int mt = 0; mt < 2; mt++)
#pragma unroll
        for (int nt = 0; nt < 4; nt++)
#pragma unroll
            for (int i = 0; i < 4; i++) acc[mt][nt][i] = 0.0f;

    // Prefetch mapping
    const int a_row0 = tid >> 2;             // chunk/4 for c = tid
    const int a_ko0 = (tid & 3) * 8;
    const int a_row1 = (tid + 256) >> 2;
    const int a_ko1 = ((tid + 256) & 3) * 8;
    const int b_k = tid >> 3;                // 0..31
    const int b_no = (tid & 7) * 8;

    auto prefetch = [&](int s, int k0) {
        __nv_bfloat16* st = smem_buf + s * STAGE_ELEMS;
        cp16(&st[AH_OFF + a_row0 * ASTR + a_ko0], &g_Wh[(size_t)(bm + a_row0) * CIN + k0 + a_ko0]);
        cp16(&st[AH_OFF + a_row1 * ASTR + a_ko1], &g_Wh[(size_t)(bm + a_row1) * CIN + k0 + a_ko1]);
        cp16(&st[AL_OFF + a_row0 * ASTR + a_ko0], &g_Wl[(size_t)(bm + a_row0) * CIN + k0 + a_ko0]);
        cp16(&st[AL_OFF + a_row1 * ASTR + a_ko1], &g_Wl[(size_t)(bm + a_row1) * CIN + k0 + a_ko1]);
        cp16(&st[BH_OFF + b_k * BSTR + b_no], &g_Bh[(size_t)(k0 + b_k) * NPAD + bn + b_no]);
        cp16(&st[BL_OFF + b_k * BSTR + b_no], &g_Bl[(size_t)(k0 + b_k) * NPAD + bn + b_no]);
        asm volatile("cp.async.commit_group;\n");
    };

    prefetch(0, 0);

    for (int ks = 0; ks < KSTEPS; ks++) {
        if (ks + 1 < KSTEPS) {
            prefetch((ks + 1) & 1, (ks + 1) * BK);
            asm volatile("cp.async.wait_group 1;\n");
        } else {
            asm volatile("cp.async.wait_group 0;\n");
        }
        __syncthreads();

        const __nv_bfloat16* st = smem_buf + (ks & 1) * STAGE_ELEMS;
        const unsigned short* sAh = (const unsigned short*)(st + AH_OFF);
        const unsigned short* sAl = (const unsigned short*)(st + AL_OFF);
        const unsigned short* sBh = (const unsigned short*)(st + BH_OFF);
        const unsigned short* sBl = (const unsigned short*)(st + BL_OFF);

#pragma unroll
        for (int h = 0; h < 2; h++) {
            const int kb = h * 16;
            unsigned ah[2][4], al[2][4];
#pragma unroll
            for (int mt = 0; mt < 2; mt++) {
                int r0 = wm * 32 + mt * 16 + frow;
                ah[mt][0] = *(const unsigned*)&sAh[(r0)     * ASTR + kb + fcolp];
                ah[mt][1] = *(const unsigned*)&sAh[(r0 + 8) * ASTR + kb + fcolp];
                ah[mt][2] = *(const unsigned*)&sAh[(r0)     * ASTR + kb + 8 + fcolp];
                ah[mt][3] = *(const unsigned*)&sAh[(r0 + 8) * ASTR + kb + 8 + fcolp];
                al[mt][0] = *(const unsigned*)&sAl[(r0)     * ASTR + kb + fcolp];
                al[mt][1] = *(const unsigned*)&sAl[(r0 + 8) * ASTR + kb + fcolp];
                al[mt][2] = *(const unsigned*)&sAl[(r0)     * ASTR + kb + 8 + fcolp];
                al[mt][3] = *(const unsigned*)&sAl[(r0 + 8) * ASTR + kb + 8 + fcolp];
            }
#pragma unroll
            for (int nt = 0; nt < 4; nt++) {
                int n = wn * 32 + nt * 8 + (lane >> 2);
                int kk = kb + fcolp;
                unsigned bh0 = (unsigned)sBh[(kk)     * BSTR + n] | ((unsigned)sBh[(kk + 1) * BSTR + n] << 16);
                unsigned bh1 = (unsigned)sBh[(kk + 8) * BSTR + n] | ((unsigned)sBh[(kk + 9) * BSTR + n] << 16);
                unsigned bl0 = (unsigned)sBl[(kk)     * BSTR + n] | ((unsigned)sBl[(kk + 1) * BSTR + n] << 16);
                unsigned bl1 = (unsigned)sBl[(kk + 8) * BSTR + n] | ((unsigned)sBl[(kk + 9) * BSTR + n] << 16);
#pragma unroll
                for (int mt = 0; mt < 2; mt++) {
                    MMA_BF16(acc[mt][nt], ah[mt], bh0, bh1);
                    MMA_BF16(acc[mt][nt], ah[mt], bl0, bl1);
                    MMA_BF16(acc[mt][nt], al[mt], bh0, bh1);
                }
            }
        }
        __syncthreads();
    }

    // Epilogue: bias + BN + exact GELU, write fp32 G [COUT][NCOLS]
#pragma unroll
    for (int mt = 0; mt < 2; mt++) {
        int r0g = bm + wm * 32 + mt * 16 + frow;
#pragma unroll
        for (int half = 0; half < 2; half++) {
            int o = r0g + half * 8;
            float inv = gamma[o] * rsqrtf(rvar[o] + 1e-6f);
            float b0 = bias[o];
            float mu = rmean[o];
            float be = beta[o];
#pragma unroll
            for (int nt = 0; nt < 4; nt++) {
                int n = bn + wn * 32 + nt * 8 + fcolp;
                if (n < NCOLS) {
                    float v0 = acc[mt][nt][half * 2 + 0] + b0;
                    float v1 = acc[mt][nt][half * 2 + 1] + b0;
                    v0 = (v0 - mu) * inv + be;
                    v1 = (v1 - mu) * inv + be;
                    v0 = v0 * normcdff(v0);
                    v1 = v1 * normcdff(v1);
                    *(float2*)&g_G[(size_t)o * NCOLS + n] = make_float2(v0, v1);
                }
            }
        }
    }
}

// ---------------------------------------------------------------------------
// Kernel 3: ROI-align + windowed place + residual add.
// ---------------------------------------------------------------------------
__device__ __forceinline__ float bilin(const float* tile, float py, float px) {
    if (py < -1.0f || py > (float)HF || px < -1.0f || px > (float)WF) return 0.0f;
    float yc = fminf(fmaxf(py, 0.0f), (float)(HF - 1));
    float xc = fminf(fmaxf(px, 0.0f), (float)(WF - 1));
    int y0 = (int)floorf(yc);
    int x0 = (int)floorf(xc);
    int y1i = min(y0 + 1, HF - 1);
    int x1i = min(x0 + 1, WF - 1);
    float ly = yc - (float)y0;
    float lx = xc - (float)x0;
    float v00 = tile[y0 * WF + x0];
    float v01 = tile[y0 * WF + x1i];
    float v10 = tile[y1i * WF + x0];
    float v11 = tile[y1i * WF + x1i];
    return (1.f - ly) * ((1.f - lx) * v00 + lx * v01)
         + ly * ((1.f - lx) * v10 + lx * v11);
}

__global__ void __launch_bounds__(224) roi_place_kernel(
    const float* __restrict__ x_t,
    const float* __restrict__ rois,
    float* __restrict__ out)
{
    __shared__ float tile[PLANE];
    const int c = blockIdx.x;
    const int t = blockIdx.y;
    const int tid = threadIdx.x;

    const float* plane = x_t + (size_t)(c * TT + t) * PLANE;
    if (tid < PLANE) tile[tid] = plane[tid];

    const float SCALE = 1.0f / 16.0f;
    float bx1 = rois[t * 4 + 0] * SCALE;
    float by1 = rois[t * 4 + 1] * SCALE;
    float bx2 = rois[t * 4 + 2] * SCALE;
    float by2 = rois[t * 4 + 3] * SCALE;
    float rw = fmaxf(bx2 - bx1, 1.0f);
    float rh = fmaxf(by2 - by1, 1.0f);
    float bw = rw / (float)NOUT;
    float bh = rh / (float)NOUT;

    int sxi = (int)floorf(bx1);
    int syi = (int)floorf(by1);
    int exi = (int)ceilf(bx2);
    int eyi = (int)ceilf(by2);
    int ml = (sxi + NOUT < HF) ? sxi : (exi - NOUT);
    int mt = (syi + NOUT < HF) ? syi : (eyi - NOUT);

    __syncthreads();

    if (tid < PLANE) {
        int h = tid / WF;
        int w = tid - h * WF;
        float xval = tile[tid];
        float val = 0.0f;
        int oy = h - mt;
        int ox = w - ml;
        if (oy >= 0 && oy < NOUT && ox >= 0 && ox < NOUT) {
            float mr = 0.0f;
#pragma unroll
            for (int s = 0; s < 2; s++) {
                float py = by1 + ((float)oy + ((float)s + 0.5f) * 0.5f) * bh;
#pragma unroll
                for (int r = 0; r < 2; r++) {
                    float px = bx1 + ((float)ox + ((float)r + 0.5f) * 0.5f) * bw;
                    mr += bilin(tile, py, px);
                }
            }
            mr *= 0.25f;
            float g = g_G[(size_t)c * NCOLS + t * (NOUT * NOUT) + oy * NOUT + ox];
            val = g * mr;
        }
        out[(size_t)(c * TT + t) * PLANE + tid] = xval + val;
    }
}

// ---------------------------------------------------------------------------
// Launch
// ---------------------------------------------------------------------------
extern "C" void kernel_launch(void* const* d_in, const int* in_sizes, int n_in,
                              void* d_out, int out_size) {
    const float* y      = (const float*)d_in[0];
    const float* x_t    = (const float*)d_in[1];
    const float* rois   = (const float*)d_in[2];
    const float* conv_w = (const float*)d_in[3];
    const float* conv_b = (const float*)d_in[4];
    const float* gamma  = (const float*)d_in[5];
    const float* beta   = (const float*)d_in[6];
    const float* rmean  = (const float*)d_in[7];
    const float* rvar   = (const float*)d_in[8];
    float* out = (float*)d_out;

    // 0) convert W to bf16 hi/lo
    {
        int n4 = (COUT * CIN) / 4;
        convert_w_kernel<<<(n4 + 255) / 256, 256>>>(conv_w);
    }
    // 1) pack subsampled y to bf16 hi/lo (k-major, padded)
    {
        int n = CIN * NPAD;
        pack_kernel<<<(n + 255) / 256, 256>>>(y);
    }
    // 2) tensor-core GEMM + BN + GELU
    {
        cudaFuncSetAttribute(gemm_bn_gelu_kernel,
                             cudaFuncAttributeMaxDynamicSharedMemorySize, SMEM_BYTES);
        dim3 grid(NPAD / BN, COUT / BM);  // (13, 24)
        gemm_bn_gelu_kernel<<<grid, 256, SMEM_BYTES>>>(conv_b, gamma, beta, rmean, rvar);
    }
    // 3) ROI-align + place + residual
    {
        dim3 grid(COUT, TT);
        roi_place_kernel<<<grid, 224>>>(x_t, rois, out);
    }
}

// round 3
// speedup vs baseline: 1.8443x; 1.1238x over previous
#include <cuda_runtime.h>
#include <cuda_bf16.h>
#include <math.h>

// Problem constants
#define CIN   1536
#define COUT  3072
#define TT    16
#define HF    14
#define WF    14
#define NOUT  7
#define NCELL (NOUT * NOUT)        // 49
#define NCOLS (TT * NCELL)         // 784
#define NPAD  832                  // 13 * 64
#define PLANE (HF * WF)            // 196

// ---------------------------------------------------------------------------
// Device scratch (no allocation allowed)
// ---------------------------------------------------------------------------
__device__ __align__(16) __nv_bfloat16 g_Wh[COUT * CIN];
__device__ __align__(16) __nv_bfloat16 g_Wl[COUT * CIN];
__device__ __align__(16) __nv_bfloat16 g_Bh[CIN * NPAD];
__device__ __align__(16) __nv_bfloat16 g_Bl[CIN * NPAD];
__device__ __align__(16) float g_G[COUT * NCOLS];
// ROI tap tables (per t): 49 cells x 16 taps
__device__ float g_tapw[TT * NCELL * 16];
__device__ int   g_tapi[TT * NCELL * 16];
__device__ int   g_win[TT * 2];          // mt, ml per t

// ---------------------------------------------------------------------------
// Kernel P: merged convert_w + pack (independent work, one launch)
// ---------------------------------------------------------------------------
#define W4CNT ((COUT * CIN) / 4)
#define W4BLK ((W4CNT + 255) / 256)          // 4608
#define PKCNT (CIN * NPAD)
#define PKBLK ((PKCNT + 255) / 256)          // 4992

__global__ void prep_kernel(const float* __restrict__ W, const float* __restrict__ y) {
    if (blockIdx.x < W4BLK) {
        int i = blockIdx.x * 256 + threadIdx.x;
        if (i >= W4CNT) return;
        float4 v = ((const float4*)W)[i];
        __nv_bfloat16 h0 = __float2bfloat16_rn(v.x);
        __nv_bfloat16 h1 = __float2bfloat16_rn(v.y);
        __nv_bfloat16 h2 = __float2bfloat16_rn(v.z);
        __nv_bfloat16 h3 = __float2bfloat16_rn(v.w);
        __nv_bfloat16 l0 = __float2bfloat16_rn(v.x - __bfloat162float(h0));
        __nv_bfloat16 l1 = __float2bfloat16_rn(v.y - __bfloat162float(h1));
        __nv_bfloat16 l2 = __float2bfloat16_rn(v.z - __bfloat162float(h2));
        __nv_bfloat16 l3 = __float2bfloat16_rn(v.w - __bfloat162float(h3));
        __nv_bfloat162* Wh2 = (__nv_bfloat162*)g_Wh;
        __nv_bfloat162* Wl2 = (__nv_bfloat162*)g_Wl;
        Wh2[i * 2 + 0] = __nv_bfloat162{h0, h1};
        Wh2[i * 2 + 1] = __nv_bfloat162{h2, h3};
        Wl2[i * 2 + 0] = __nv_bfloat162{l0, l1};
        Wl2[i * 2 + 1] = __nv_bfloat162{l2, l3};
    } else {
        int idx = (blockIdx.x - W4BLK) * 256 + threadIdx.x;
        if (idx >= PKCNT) return;
        int k = idx / NPAD;
        int n = idx - k * NPAD;
        float v = 0.0f;
        if (n < NCOLS) {
            int t = n / NCELL;
            int r = n - t * NCELL;
            int oy = r / NOUT;
            int ox = r - oy * NOUT;
            v = y[((k * TT + t) * HF + 2 * oy) * WF + 2 * ox];
        }
        __nv_bfloat16 h = __float2bfloat16_rn(v);
        g_Bh[idx] = h;
        g_Bl[idx] = __float2bfloat16_rn(v - __bfloat162float(h));
    }
}

// ---------------------------------------------------------------------------
// Kernel T: precompute per-t ROI tap tables + window offsets
// grid=TT, block=NCELL
// ---------------------------------------------------------------------------
__global__ void taps_kernel(const float* __restrict__ rois) {
    const int t = blockIdx.x;
    const int cell = threadIdx.x;      // 0..48
    const float SC = 1.0f / 16.0f;
    float bx1 = rois[t * 4 + 0] * SC;
    float by1 = rois[t * 4 + 1] * SC;
    float bx2 = rois[t * 4 + 2] * SC;
    float by2 = rois[t * 4 + 3] * SC;
    float rw = fmaxf(bx2 - bx1, 1.0f);
    float rh = fmaxf(by2 - by1, 1.0f);
    float bw = rw / (float)NOUT;
    float bh = rh / (float)NOUT;

    if (cell == 0) {
        int sxi = (int)floorf(bx1);
        int syi = (int)floorf(by1);
        int exi = (int)ceilf(bx2);
        int eyi = (int)ceilf(by2);
        g_win[t * 2 + 0] = (syi + NOUT < HF) ? syi : (eyi - NOUT);  // mt
        g_win[t * 2 + 1] = (sxi + NOUT < HF) ? sxi : (exi - NOUT);  // ml
    }

    int oy = cell / NOUT;
    int ox = cell - oy * NOUT;
    float* tw = g_tapw + (t * NCELL + cell) * 16;
    int*   ti = g_tapi + (t * NCELL + cell) * 16;

#pragma unroll
    for (int s = 0; s < 2; s++) {
#pragma unroll
        for (int r = 0; r < 2; r++) {
            int base = (s * 2 + r) * 4;
            float py = by1 + ((float)oy + ((float)s + 0.5f) * 0.5f) * bh;
            float px = bx1 + ((float)ox + ((float)r + 0.5f) * 0.5f) * bw;
            bool oob = (py < -1.0f) | (py > (float)HF) | (px < -1.0f) | (px > (float)WF);
            if (oob) {
                tw[base + 0] = 0.f; tw[base + 1] = 0.f; tw[base + 2] = 0.f; tw[base + 3] = 0.f;
                ti[base + 0] = 0;   ti[base + 1] = 0;   ti[base + 2] = 0;   ti[base + 3] = 0;
            } else {
                float yc = fminf(fmaxf(py, 0.0f), (float)(HF - 1));
                float xc = fminf(fmaxf(px, 0.0f), (float)(WF - 1));
                int y0 = (int)floorf(yc);
                int x0 = (int)floorf(xc);
                int y1i = min(y0 + 1, HF - 1);
                int x1i = min(x0 + 1, WF - 1);
                float ly = yc - (float)y0;
                float lx = xc - (float)x0;
                tw[base + 0] = 0.25f * (1.f - ly) * (1.f - lx);
                tw[base + 1] = 0.25f * (1.f - ly) * lx;
                tw[base + 2] = 0.25f * ly * (1.f - lx);
                tw[base + 3] = 0.25f * ly * lx;
                ti[base + 0] = y0 * WF + x0;
                ti[base + 1] = y0 * WF + x1i;
                ti[base + 2] = y1i * WF + x0;
                ti[base + 3] = y1i * WF + x1i;
            }
        }
    }
}

// ---------------------------------------------------------------------------
// Kernel 2: split-bf16 tensor-core GEMM + bias + BN + exact GELU
// BM=128, BN=64, BK=32; 256 threads; ldmatrix fragments; cp.async dbl-buffer
// ---------------------------------------------------------------------------
#define BM 128
#define BN 64
#define BK 32
#define KSTEPS (CIN / BK)     // 48
#define ASTR 40               // padded k-stride for A (bf16) -> 80B rows
#define BSTR 72               // padded n-stride for B (bf16) -> 144B rows

#define AH_OFF 0
#define AL_OFF (BM * ASTR)
#define BH_OFF (2 * BM * ASTR)
#define BL_OFF (BH_OFF + BK * BSTR)
#define STAGE_ELEMS (BL_OFF + BK * BSTR)
#define SMEM_BYTES (2 * STAGE_ELEMS * 2)

__device__ __forceinline__ void cp16(void* smem, const void* gmem) {
    unsigned sa = (unsigned)__cvta_generic_to_shared(smem);
    asm volatile("cp.async.cg.shared.global [%0], [%1], 16;\n" :: "r"(sa), "l"(gmem));
}
__device__ __forceinline__ void ldsm4(unsigned* r, const void* p) {
    unsigned a = (unsigned)__cvta_generic_to_shared(p);
    asm volatile("ldmatrix.sync.aligned.m8n8.x4.shared.b16 {%0,%1,%2,%3}, [%4];\n"
        : "=r"(r[0]), "=r"(r[1]), "=r"(r[2]), "=r"(r[3]) : "r"(a));
}
__device__ __forceinline__ void ldsm4t(unsigned* r, const void* p) {
    unsigned a = (unsigned)__cvta_generic_to_shared(p);
    asm volatile("ldmatrix.sync.aligned.m8n8.x4.trans.shared.b16 {%0,%1,%2,%3}, [%4];\n"
        : "=r"(r[0]), "=r"(r[1]), "=r"(r[2]), "=r"(r[3]) : "r"(a));
}

#define MMA_BF16(c, a, b0, b1)                                              \
    asm volatile(                                                           \
        "mma.sync.aligned.m16n8k16.row.col.f32.bf16.bf16.f32 "              \
        "{%0,%1,%2,%3}, {%4,%5,%6,%7}, {%8,%9}, {%0,%1,%2,%3};\n"           \
        : "+f"(c[0]), "+f"(c[1]), "+f"(c[2]), "+f"(c[3])                    \
        : "r"(a[0]), "r"(a[1]), "r"(a[2]), "r"(a[3]), "r"(b0), "r"(b1))

extern __shared__ __nv_bfloat16 smem_buf[];

__global__ void __launch_bounds__(256) gemm_bn_gelu_kernel(
    const float* __restrict__ bias,
    const float* __restrict__ gamma,
    const float* __restrict__ beta,
    const float* __restrict__ rmean,
    const float* __restrict__ rvar)
{
    const int tid = threadIdx.x;
    const int bm = blockIdx.y * BM;
    const int bn = blockIdx.x * BN;

    const int lane = tid & 31;
    const int warp = tid >> 5;
    const int wm = warp >> 1;       // 0..3
    const int wn = warp & 1;        // 0..1
    const int frow = lane >> 2;
    const int fcolp = (lane & 3) * 2;
    const int sel = lane >> 3;      // ldmatrix quad select
    const int lr = lane & 7;

    float acc[2][4][4];
#pragma unroll
    for (int mt = 0; mt < 2; mt++)
#pragma unroll
        for (int nt = 0; nt < 4; nt++)
#pragma unroll
            for (int i = 0; i < 4; i++) acc[mt][nt][i] = 0.0f;

    const int a_row0 = tid >> 2;
    const int a_ko0 = (tid & 3) * 8;
    const int a_row1 = (tid + 256) >> 2;
    const int a_ko1 = ((tid + 256) & 3) * 8;
    const int b_k = tid >> 3;
    const int b_no = (tid & 7) * 8;

    auto prefetch = [&](int s, int k0) {
        __nv_bfloat16* st = smem_buf + s * STAGE_ELEMS;
        cp16(&st[AH_OFF + a_row0 * ASTR + a_ko0], &g_Wh[(size_t)(bm + a_row0) * CIN + k0 + a_ko0]);
        cp16(&st[AH_OFF + a_row1 * ASTR + a_ko1], &g_Wh[(size_t)(bm + a_row1) * CIN + k0 + a_ko1]);
        cp16(&st[AL_OFF + a_row0 * ASTR + a_ko0], &g_Wl[(size_t)(bm + a_row0) * CIN + k0 + a_ko0]);
        cp16(&st[AL_OFF + a_row1 * ASTR + a_ko1], &g_Wl[(size_t)(bm + a_row1) * CIN + k0 + a_ko1]);
        cp16(&st[BH_OFF + b_k * BSTR + b_no], &g_Bh[(size_t)(k0 + b_k) * NPAD + bn + b_no]);
        cp16(&st[BL_OFF + b_k * BSTR + b_no], &g_Bl[(size_t)(k0 + b_k) * NPAD + bn + b_no]);
        asm volatile("cp.async.commit_group;\n");
    };

    prefetch(0, 0);

    for (int ks = 0; ks < KSTEPS; ks++) {
        if (ks + 1 < KSTEPS) {
            prefetch((ks + 1) & 1, (ks + 1) * BK);
            asm volatile("cp.async.wait_group 1;\n");
        } else {
            asm volatile("cp.async.wait_group 0;\n");
        }
        __syncthreads();

        const __nv_bfloat16* st = smem_buf + (ks & 1) * STAGE_ELEMS;
        const unsigned short* sAh = (const unsigned short*)(st + AH_OFF);
        const unsigned short* sAl = (const unsigned short*)(st + AL_OFF);
        const unsigned short* sBh = (const unsigned short*)(st + BH_OFF);
        const unsigned short* sBl = (const unsigned short*)(st + BL_OFF);

#pragma unroll
        for (int h = 0; h < 2; h++) {
            const int kb = h * 16;
            unsigned ah[2][4], al[2][4], bh[2][4], bl[2][4];
            const int arow = (sel & 1) * 8 + lr;
            const int akof = (sel >> 1) * 8;
#pragma unroll
            for (int mt = 0; mt < 2; mt++) {
                int r = wm * 32 + mt * 16 + arow;
                ldsm4(ah[mt], &sAh[r * ASTR + kb + akof]);
                ldsm4(al[mt], &sAl[r * ASTR + kb + akof]);
            }
#pragma unroll
            for (int np = 0; np < 2; np++) {
                int kr = kb + (sel & 1) * 8 + lr;
                int nc = wn * 32 + np * 16 + (sel >> 1) * 8;
                ldsm4t(bh[np], &sBh[kr * BSTR + nc]);
                ldsm4t(bl[np], &sBl[kr * BSTR + nc]);
            }
#pragma unroll
            for (int np = 0; np < 2; np++)
#pragma unroll
                for (int q = 0; q < 2; q++) {
                    int nt = np * 2 + q;
#pragma unroll
                    for (int mt = 0; mt < 2; mt++) {
                        MMA_BF16(acc[mt][nt], ah[mt], bh[np][q * 2], bh[np][q * 2 + 1]);
                        MMA_BF16(acc[mt][nt], ah[mt], bl[np][q * 2], bl[np][q * 2 + 1]);
                        MMA_BF16(acc[mt][nt], al[mt], bh[np][q * 2], bh[np][q * 2 + 1]);
                    }
                }
        }
        __syncthreads();
    }

    // Epilogue: bias + BN + exact GELU
#pragma unroll
    for (int mt = 0; mt < 2; mt++) {
        int r0g = bm + wm * 32 + mt * 16 + frow;
#pragma unroll
        for (int half = 0; half < 2; half++) {
            int o = r0g + half * 8;
            float inv = gamma[o] * rsqrtf(rvar[o] + 1e-6f);
            float b0 = bias[o];
            float mu = rmean[o];
            float be = beta[o];
#pragma unroll
            for (int nt = 0; nt < 4; nt++) {
                int n = bn + wn * 32 + nt * 8 + fcolp;
                if (n < NCOLS) {
                    float v0 = acc[mt][nt][half * 2 + 0] + b0;
                    float v1 = acc[mt][nt][half * 2 + 1] + b0;
                    v0 = (v0 - mu) * inv + be;
                    v1 = (v1 - mu) * inv + be;
                    v0 = v0 * normcdff(v0);
                    v1 = v1 * normcdff(v1);
                    *(float2*)&g_G[(size_t)o * NCOLS + n] = make_float2(v0, v1);
                }
            }
        }
    }
}

// ---------------------------------------------------------------------------
// Kernel 3: ROI-align (table-driven) + windowed place + residual add
// 8 channels per block, float4 I/O. grid (COUT/8, TT), 256 threads.
// ---------------------------------------------------------------------------
#define CH 8
#define PL4 (PLANE / 4 > 0 ? 49 : 49)   // 49 float4 per plane

__global__ void __launch_bounds__(256) roi_place_kernel(
    const float* __restrict__ x_t,
    float* __restrict__ out)
{
    __shared__ float s_tw[NCELL * 16];
    __shared__ int   s_ti[NCELL * 16];
    __shared__ __align__(16) float tile[CH][PLANE];
    __shared__ float wsm[CH][NCELL];

    const int t = blockIdx.y;
    const int c0 = blockIdx.x * CH;
    const int tid = threadIdx.x;

    // tap table for this t
    for (int i = tid; i < NCELL * 16; i += 256) {
        s_tw[i] = g_tapw[t * NCELL * 16 + i];
        s_ti[i] = g_tapi[t * NCELL * 16 + i];
    }
    // planes (each plane = 49 aligned float4)
    const float4* src4 = (const float4*)x_t;
    for (int i = tid; i < CH * 49; i += 256) {
        int c = i / 49, q = i - (i / 49) * 49;
        ((float4*)tile[c])[q] = src4[(size_t)((c0 + c) * TT + t) * 49 + q];
    }
    __syncthreads();

    // weighted = gelu(conv) * roi_mean per window cell
    for (int j = tid; j < CH * NCELL; j += 256) {
        int p = j / NCELL, cell = j - (j / NCELL) * NCELL;
        const float* tp = tile[p];
        const float* tw = s_tw + cell * 16;
        const int* ti = s_ti + cell * 16;
        float mr = 0.0f;
#pragma unroll
        for (int k = 0; k < 16; k++) mr = fmaf(tw[k], tp[ti[k]], mr);
        float g = g_G[(size_t)(c0 + p) * NCOLS + t * NCELL + cell];
        wsm[p][cell] = g * mr;
    }
    __syncthreads();

    const int mt = g_win[t * 2 + 0];
    const int ml = g_win[t * 2 + 1];
    float4* dst4 = (float4*)out;
    for (int i = tid; i < CH * 49; i += 256) {
        int c = i / 49, q = i - (i / 49) * 49;
        float4 v = ((float4*)tile[c])[q];
        float* vp = (float*)&v;
        int e0 = q * 4;
#pragma unroll
        for (int j = 0; j < 4; j++) {
            int e = e0 + j;
            int h = e / WF;
            int w = e - h * WF;
            int oy = h - mt, ox = w - ml;
            if (oy >= 0 && oy < NOUT && ox >= 0 && ox < NOUT)
                vp[j] += wsm[c][oy * NOUT + ox];
        }
        dst4[(size_t)((c0 + c) * TT + t) * 49 + q] = v;
    }
}

// ---------------------------------------------------------------------------
// Launch
// ---------------------------------------------------------------------------
extern "C" void kernel_launch(void* const* d_in, const int* in_sizes, int n_in,
                              void* d_out, int out_size) {
    const float* y      = (const float*)d_in[0];
    const float* x_t    = (const float*)d_in[1];
    const float* rois   = (const float*)d_in[2];
    const float* conv_w = (const float*)d_in[3];
    const float* conv_b = (const float*)d_in[4];
    const float* gamma  = (const float*)d_in[5];
    const float* beta   = (const float*)d_in[6];
    const float* rmean  = (const float*)d_in[7];
    const float* rvar   = (const float*)d_in[8];
    float* out = (float*)d_out;

    // P) convert W + pack y (merged)
    prep_kernel<<<W4BLK + PKBLK, 256>>>(conv_w, y);
    // T) ROI tap tables
    taps_kernel<<<TT, NCELL>>>(rois);
    // 2) tensor-core GEMM + BN + GELU
    {
        cudaFuncSetAttribute(gemm_bn_gelu_kernel,
                             cudaFuncAttributeMaxDynamicSharedMemorySize, SMEM_BYTES);
        dim3 grid(NPAD / BN, COUT / BM);  // (13, 24)
        gemm_bn_gelu_kernel<<<grid, 256, SMEM_BYTES>>>(conv_b, gamma, beta, rmean, rvar);
    }
    // 3) ROI-align + place + residual
    {
        dim3 grid(COUT / CH, TT);
        roi_place_kernel<<<grid, 256>>>(x_t, out);
    }
}

// round 4
// speedup vs baseline: 1.8676x; 1.0126x over previous
#include <cuda_runtime.h>
#include <cuda_bf16.h>
#include <math.h>

// Problem constants
#define CIN   1536
#define COUT  3072
#define TT    16
#define HF    14
#define WF    14
#define NOUT  7
#define NCELL (NOUT * NOUT)        // 49
#define NCOLS (TT * NCELL)         // 784
#define NPAD  832                  // 13 * 64
#define PLANE (HF * WF)            // 196

// ---------------------------------------------------------------------------
// Device scratch
// ---------------------------------------------------------------------------
__device__ __align__(16) __nv_bfloat16 g_Wh[COUT * CIN];
__device__ __align__(16) __nv_bfloat16 g_Wl[COUT * CIN];
__device__ __align__(16) __nv_bfloat16 g_Bh[CIN * NPAD];
__device__ __align__(16) __nv_bfloat16 g_Bl[CIN * NPAD];
__device__ __align__(16) float g_G[COUT * NCOLS];
__device__ __align__(16) float g_tapw[TT * NCELL * 16];
__device__ __align__(16) int   g_tapi[TT * NCELL * 16];
__device__ int   g_win[TT * 2];          // mt, ml per t

// ---------------------------------------------------------------------------
// Kernel P: merged convert_w + pack + taps
// ---------------------------------------------------------------------------
#define W4CNT ((COUT * CIN) / 4)
#define W4BLK ((W4CNT + 255) / 256)          // 4608
#define PKCNT (CIN * NPAD)
#define PKBLK ((PKCNT + 255) / 256)          // 4992

__global__ void prep_kernel(const float* __restrict__ W, const float* __restrict__ y,
                            const float* __restrict__ rois) {
    if (blockIdx.x < W4BLK) {
        int i = blockIdx.x * 256 + threadIdx.x;
        if (i >= W4CNT) return;
        float4 v = ((const float4*)W)[i];
        __nv_bfloat16 h0 = __float2bfloat16_rn(v.x);
        __nv_bfloat16 h1 = __float2bfloat16_rn(v.y);
        __nv_bfloat16 h2 = __float2bfloat16_rn(v.z);
        __nv_bfloat16 h3 = __float2bfloat16_rn(v.w);
        __nv_bfloat16 l0 = __float2bfloat16_rn(v.x - __bfloat162float(h0));
        __nv_bfloat16 l1 = __float2bfloat16_rn(v.y - __bfloat162float(h1));
        __nv_bfloat16 l2 = __float2bfloat16_rn(v.z - __bfloat162float(h2));
        __nv_bfloat16 l3 = __float2bfloat16_rn(v.w - __bfloat162float(h3));
        __nv_bfloat162* Wh2 = (__nv_bfloat162*)g_Wh;
        __nv_bfloat162* Wl2 = (__nv_bfloat162*)g_Wl;
        Wh2[i * 2 + 0] = __nv_bfloat162{h0, h1};
        Wh2[i * 2 + 1] = __nv_bfloat162{h2, h3};
        Wl2[i * 2 + 0] = __nv_bfloat162{l0, l1};
        Wl2[i * 2 + 1] = __nv_bfloat162{l2, l3};
    } else if (blockIdx.x < W4BLK + PKBLK) {
        int idx = (blockIdx.x - W4BLK) * 256 + threadIdx.x;
        if (idx >= PKCNT) return;
        int k = idx / NPAD;
        int n = idx - k * NPAD;
        float v = 0.0f;
        if (n < NCOLS) {
            int t = n / NCELL;
            int r = n - t * NCELL;
            int oy = r / NOUT;
            int ox = r - oy * NOUT;
            v = y[((k * TT + t) * HF + 2 * oy) * WF + 2 * ox];
        }
        __nv_bfloat16 h = __float2bfloat16_rn(v);
        g_Bh[idx] = h;
        g_Bl[idx] = __float2bfloat16_rn(v - __bfloat162float(h));
    } else {
        // taps: one block per t, 49 active threads
        const int t = blockIdx.x - (W4BLK + PKBLK);
        const int cell = threadIdx.x;
        if (cell >= NCELL) return;
        const float SC = 1.0f / 16.0f;
        float bx1 = rois[t * 4 + 0] * SC;
        float by1 = rois[t * 4 + 1] * SC;
        float bx2 = rois[t * 4 + 2] * SC;
        float by2 = rois[t * 4 + 3] * SC;
        float bw = fmaxf(bx2 - bx1, 1.0f) / (float)NOUT;
        float bh = fmaxf(by2 - by1, 1.0f) / (float)NOUT;

        if (cell == 0) {
            int sxi = (int)floorf(bx1);
            int syi = (int)floorf(by1);
            int exi = (int)ceilf(bx2);
            int eyi = (int)ceilf(by2);
            g_win[t * 2 + 0] = (syi + NOUT < HF) ? syi : (eyi - NOUT);  // mt
            g_win[t * 2 + 1] = (sxi + NOUT < HF) ? sxi : (exi - NOUT);  // ml
        }

        int oy = cell / NOUT;
        int ox = cell - oy * NOUT;
        float* tw = g_tapw + (t * NCELL + cell) * 16;
        int*   ti = g_tapi + (t * NCELL + cell) * 16;

#pragma unroll
        for (int s = 0; s < 2; s++) {
#pragma unroll
            for (int r = 0; r < 2; r++) {
                int base = (s * 2 + r) * 4;
                float py = by1 + ((float)oy + ((float)s + 0.5f) * 0.5f) * bh;
                float px = bx1 + ((float)ox + ((float)r + 0.5f) * 0.5f) * bw;
                bool oob = (py < -1.0f) | (py > (float)HF) | (px < -1.0f) | (px > (float)WF);
                if (oob) {
                    tw[base + 0] = 0.f; tw[base + 1] = 0.f; tw[base + 2] = 0.f; tw[base + 3] = 0.f;
                    ti[base + 0] = 0;   ti[base + 1] = 0;   ti[base + 2] = 0;   ti[base + 3] = 0;
                } else {
                    float yc = fminf(fmaxf(py, 0.0f), (float)(HF - 1));
                    float xc = fminf(fmaxf(px, 0.0f), (float)(WF - 1));
                    int y0 = (int)floorf(yc);
                    int x0 = (int)floorf(xc);
                    int y1i = min(y0 + 1, HF - 1);
                    int x1i = min(x0 + 1, WF - 1);
                    float ly = yc - (float)y0;
                    float lx = xc - (float)x0;
                    tw[base + 0] = 0.25f * (1.f - ly) * (1.f - lx);
                    tw[base + 1] = 0.25f * (1.f - ly) * lx;
                    tw[base + 2] = 0.25f * ly * (1.f - lx);
                    tw[base + 3] = 0.25f * ly * lx;
                    ti[base + 0] = y0 * WF + x0;
                    ti[base + 1] = y0 * WF + x1i;
                    ti[base + 2] = y1i * WF + x0;
                    ti[base + 3] = y1i * WF + x1i;
                }
            }
        }
    }
}

// ---------------------------------------------------------------------------
// Kernel 2: split-bf16 tensor-core GEMM + bias + BN + exact GELU
// BM=128, BN=64, BK=32; 256 threads; ldmatrix; 3-stage cp.async, 1 sync/iter
// ---------------------------------------------------------------------------
#define BM 128
#define BN 64
#define BK 32
#define KSTEPS (CIN / BK)     // 48
#define ASTR 40
#define BSTR 72

#define AH_OFF 0
#define AL_OFF (BM * ASTR)
#define BH_OFF (2 * BM * ASTR)
#define BL_OFF (BH_OFF + BK * BSTR)
#define STAGE_ELEMS (BL_OFF + BK * BSTR)     // 14848
#define NSTAGE 3
#define SMEM_BYTES (NSTAGE * STAGE_ELEMS * 2)  // 89088

__device__ __forceinline__ void cp16(void* smem, const void* gmem) {
    unsigned sa = (unsigned)__cvta_generic_to_shared(smem);
    asm volatile("cp.async.cg.shared.global [%0], [%1], 16;\n" :: "r"(sa), "l"(gmem));
}
__device__ __forceinline__ void ldsm4(unsigned* r, const void* p) {
    unsigned a = (unsigned)__cvta_generic_to_shared(p);
    asm volatile("ldmatrix.sync.aligned.m8n8.x4.shared.b16 {%0,%1,%2,%3}, [%4];\n"
        : "=r"(r[0]), "=r"(r[1]), "=r"(r[2]), "=r"(r[3]) : "r"(a));
}
__device__ __forceinline__ void ldsm4t(unsigned* r, const void* p) {
    unsigned a = (unsigned)__cvta_generic_to_shared(p);
    asm volatile("ldmatrix.sync.aligned.m8n8.x4.trans.shared.b16 {%0,%1,%2,%3}, [%4];\n"
        : "=r"(r[0]), "=r"(r[1]), "=r"(r[2]), "=r"(r[3]) : "r"(a));
}

#define MMA_BF16(c, a, b0, b1)                                              \
    asm volatile(                                                           \
        "mma.sync.aligned.m16n8k16.row.col.f32.bf16.bf16.f32 "              \
        "{%0,%1,%2,%3}, {%4,%5,%6,%7}, {%8,%9}, {%0,%1,%2,%3};\n"           \
        : "+f"(c[0]), "+f"(c[1]), "+f"(c[2]), "+f"(c[3])                    \
        : "r"(a[0]), "r"(a[1]), "r"(a[2]), "r"(a[3]), "r"(b0), "r"(b1))

extern __shared__ __nv_bfloat16 smem_buf[];

__global__ void __launch_bounds__(256) gemm_bn_gelu_kernel(
    const float* __restrict__ bias,
    const float* __restrict__ gamma,
    const float* __restrict__ beta,
    const float* __restrict__ rmean,
    const float* __restrict__ rvar)
{
    const int tid = threadIdx.x;
    const int bm = blockIdx.y * BM;
    const int bn = blockIdx.x * BN;

    const int lane = tid & 31;
    const int warp = tid >> 5;
    const int wm = warp >> 1;
    const int wn = warp & 1;
    const int frow = lane >> 2;
    const int fcolp = (lane & 3) * 2;
    const int sel = lane >> 3;
    const int lr = lane & 7;

    float acc[2][4][4];
#pragma unroll
    for (int mt = 0; mt < 2; mt++)
#pragma unroll
        for (int nt = 0; nt < 4; nt++)
#pragma unroll
            for (int i = 0; i < 4; i++) acc[mt][nt][i] = 0.0f;

    const int a_row0 = tid >> 2;
    const int a_ko0 = (tid & 3) * 8;
    const int a_row1 = (tid + 256) >> 2;
    const int a_ko1 = ((tid + 256) & 3) * 8;
    const int b_k = tid >> 3;
    const int b_no = (tid & 7) * 8;

    auto prefetch = [&](int s, int k0) {
        __nv_bfloat16* st = smem_buf + s * STAGE_ELEMS;
        cp16(&st[AH_OFF + a_row0 * ASTR + a_ko0], &g_Wh[(size_t)(bm + a_row0) * CIN + k0 + a_ko0]);
        cp16(&st[AH_OFF + a_row1 * ASTR + a_ko1], &g_Wh[(size_t)(bm + a_row1) * CIN + k0 + a_ko1]);
        cp16(&st[AL_OFF + a_row0 * ASTR + a_ko0], &g_Wl[(size_t)(bm + a_row0) * CIN + k0 + a_ko0]);
        cp16(&st[AL_OFF + a_row1 * ASTR + a_ko1], &g_Wl[(size_t)(bm + a_row1) * CIN + k0 + a_ko1]);
        cp16(&st[BH_OFF + b_k * BSTR + b_no], &g_Bh[(size_t)(k0 + b_k) * NPAD + bn + b_no]);
        cp16(&st[BL_OFF + b_k * BSTR + b_no], &g_Bl[(size_t)(k0 + b_k) * NPAD + bn + b_no]);
        asm volatile("cp.async.commit_group;\n");
    };

    auto consume = [&](int s) {
        const __nv_bfloat16* st = smem_buf + s * STAGE_ELEMS;
        const unsigned short* sAh = (const unsigned short*)(st + AH_OFF);
        const unsigned short* sAl = (const unsigned short*)(st + AL_OFF);
        const unsigned short* sBh = (const unsigned short*)(st + BH_OFF);
        const unsigned short* sBl = (const unsigned short*)(st + BL_OFF);
#pragma unroll
        for (int h = 0; h < 2; h++) {
            const int kb = h * 16;
            unsigned ah[2][4], al[2][4], bh[2][4], bl[2][4];
            const int arow = (sel & 1) * 8 + lr;
            const int akof = (sel >> 1) * 8;
#pragma unroll
            for (int mt = 0; mt < 2; mt++) {
                int r = wm * 32 + mt * 16 + arow;
                ldsm4(ah[mt], &sAh[r * ASTR + kb + akof]);
                ldsm4(al[mt], &sAl[r * ASTR + kb + akof]);
            }
#pragma unroll
            for (int np = 0; np < 2; np++) {
                int kr = kb + (sel & 1) * 8 + lr;
                int nc = wn * 32 + np * 16 + (sel >> 1) * 8;
                ldsm4t(bh[np], &sBh[kr * BSTR + nc]);
                ldsm4t(bl[np], &sBl[kr * BSTR + nc]);
            }
#pragma unroll
            for (int np = 0; np < 2; np++)
#pragma unroll
                for (int q = 0; q < 2; q++) {
                    int nt = np * 2 + q;
#pragma unroll
                    for (int mt = 0; mt < 2; mt++) {
                        MMA_BF16(acc[mt][nt], ah[mt], bh[np][q * 2], bh[np][q * 2 + 1]);
                        MMA_BF16(acc[mt][nt], ah[mt], bl[np][q * 2], bl[np][q * 2 + 1]);
                        MMA_BF16(acc[mt][nt], al[mt], bh[np][q * 2], bh[np][q * 2 + 1]);
                    }
                }
        }
    };

    prefetch(0, 0);
    prefetch(1, BK);

    int s = 0;
    for (int ks = 0; ks < KSTEPS - 1; ks++) {
        asm volatile("cp.async.wait_group 1;\n");
        __syncthreads();
        if (ks + 2 < KSTEPS) prefetch((s + 2) % NSTAGE, (ks + 2) * BK);
        consume(s);
        s = (s + 1) % NSTAGE;
    }
    asm volatile("cp.async.wait_group 0;\n");
    __syncthreads();
    consume(s);

    // Epilogue: bias + BN + exact GELU
#pragma unroll
    for (int mt = 0; mt < 2; mt++) {
        int r0g = bm + wm * 32 + mt * 16 + frow;
#pragma unroll
        for (int half = 0; half < 2; half++) {
            int o = r0g + half * 8;
            float inv = gamma[o] * rsqrtf(rvar[o] + 1e-6f);
            float b0 = bias[o];
            float mu = rmean[o];
            float be = beta[o];
#pragma unroll
            for (int nt = 0; nt < 4; nt++) {
                int n = bn + wn * 32 + nt * 8 + fcolp;
                if (n < NCOLS) {
                    float v0 = acc[mt][nt][half * 2 + 0] + b0;
                    float v1 = acc[mt][nt][half * 2 + 1] + b0;
                    v0 = (v0 - mu) * inv + be;
                    v1 = (v1 - mu) * inv + be;
                    v0 = v0 * normcdff(v0);
                    v1 = v1 * normcdff(v1);
                    *(float2*)&g_G[(size_t)o * NCOLS + n] = make_float2(v0, v1);
                }
            }
        }
    }
}

// ---------------------------------------------------------------------------
// Kernel 3: ROI-align (vectorized tap tables) + place + residual add
// 16 channels per block, 256 threads, grid (COUT/16, TT)
// ---------------------------------------------------------------------------
#define CH 16
#define NITEM (CH * NCELL)   // 784

__global__ void __launch_bounds__(256) roi_place_kernel(
    const float* __restrict__ x_t,
    float* __restrict__ out)
{
    __shared__ __align__(16) float s_tw[NCELL * 16];
    __shared__ __align__(16) int   s_ti[NCELL * 16];
    __shared__ __align__(16) float tile[CH][PLANE];
    __shared__ float wsm[CH][52];

    const int t = blockIdx.y;
    const int c0 = blockIdx.x * CH;
    const int tid = threadIdx.x;

    // tap tables (vector loads)
    {
        const float4* gw4 = (const float4*)(g_tapw + t * NCELL * 16);
        const int4*   gi4 = (const int4*)(g_tapi + t * NCELL * 16);
        float4* sw4 = (float4*)s_tw;
        int4*   si4 = (int4*)s_ti;
        for (int i = tid; i < NCELL * 4; i += 256) {
            sw4[i] = gw4[i];
            si4[i] = gi4[i];
        }
    }
    // planes (49 aligned float4 each)
    const float4* src4 = (const float4*)x_t;
    for (int i = tid; i < CH * 49; i += 256) {
        int c = i / 49, q = i - (i / 49) * 49;
        ((float4*)tile[c])[q] = src4[(size_t)((c0 + c) * TT + t) * 49 + q];
    }
    __syncthreads();

    // weighted = gelu(conv) * roi_mean per window cell
    for (int j = tid; j < NITEM; j += 256) {
        int p = j / NCELL, cell = j - (j / NCELL) * NCELL;
        const float* tp = tile[p];
        const float4* tw4 = (const float4*)(s_tw + cell * 16);
        const int4*   ti4 = (const int4*)(s_ti + cell * 16);
        float mr = 0.0f;
#pragma unroll
        for (int g4 = 0; g4 < 4; g4++) {
            float4 w = tw4[g4];
            int4 ix = ti4[g4];
            mr = fmaf(w.x, tp[ix.x], mr);
            mr = fmaf(w.y, tp[ix.y], mr);
            mr = fmaf(w.z, tp[ix.z], mr);
            mr = fmaf(w.w, tp[ix.w], mr);
        }
        float g = g_G[(size_t)(c0 + p) * NCOLS + t * NCELL + cell];
        wsm[p][cell] = g * mr;
    }
    __syncthreads();

    const int mt = g_win[t * 2 + 0];
    const int ml = g_win[t * 2 + 1];
    float4* dst4 = (float4*)out;
    for (int i = tid; i < CH * 49; i += 256) {
        int c = i / 49, q = i - (i / 49) * 49;
        float4 v = ((float4*)tile[c])[q];
        float* vp = (float*)&v;
        int e0 = q * 4;
#pragma unroll
        for (int j = 0; j < 4; j++) {
            int e = e0 + j;
            int h = e / WF;
            int w = e - h * WF;
            int oy = h - mt, ox = w - ml;
            if (oy >= 0 && oy < NOUT && ox >= 0 && ox < NOUT)
                vp[j] += wsm[c][oy * NOUT + ox];
        }
        dst4[(size_t)((c0 + c) * TT + t) * 49 + q] = v;
    }
}

// ---------------------------------------------------------------------------
// Launch
// ---------------------------------------------------------------------------
extern "C" void kernel_launch(void* const* d_in, const int* in_sizes, int n_in,
                              void* d_out, int out_size) {
    const float* y      = (const float*)d_in[0];
    const float* x_t    = (const float*)d_in[1];
    const float* rois   = (const float*)d_in[2];
    const float* conv_w = (const float*)d_in[3];
    const float* conv_b = (const float*)d_in[4];
    const float* gamma  = (const float*)d_in[5];
    const float* beta   = (const float*)d_in[6];
    const float* rmean  = (const float*)d_in[7];
    const float* rvar   = (const float*)d_in[8];
    float* out = (float*)d_out;

    // P) convert W + pack y + taps (merged)
    prep_kernel<<<W4BLK + PKBLK + TT, 256>>>(conv_w, y, rois);
    // 2) tensor-core GEMM + BN + GELU
    {
        cudaFuncSetAttribute(gemm_bn_gelu_kernel,
                             cudaFuncAttributeMaxDynamicSharedMemorySize, SMEM_BYTES);
        dim3 grid(NPAD / BN, COUT / BM);  // (13, 24)
        gemm_bn_gelu_kernel<<<grid, 256, SMEM_BYTES>>>(conv_b, gamma, beta, rmean, rvar);
    }
    // 3) ROI-align + place + residual
    {
        dim3 grid(COUT / CH, TT);
        roi_place_kernel<<<grid, 256>>>(x_t, out);
    }
}

// round 6
// speedup vs baseline: 2.7843x; 1.4909x over previous
#include <cuda_runtime.h>
#include <cuda_fp16.h>
#include <math.h>
#include <stdint.h>

// Problem constants
#define CIN   1536
#define COUT  3072
#define TT    16
#define HF    14
#define WF    14
#define NOUT  7
#define NCELL (NOUT * NOUT)        // 49
#define NCOLS (TT * NCELL)         // 784
#define NPAD  832                  // 13 * 64
#define PLANE (HF * WF)            // 196

// ---------------------------------------------------------------------------
// Device scratch
// ---------------------------------------------------------------------------
__device__ __align__(16) __half g_Wh[COUT * CIN];           // W fp16 (unsplit)
__device__ __align__(16) __half g_Bh[CIN * NPAD];           // y hi, k-major
__device__ __align__(16) __half g_Bl[CIN * NPAD];           // y lo
__device__ __align__(16) float g_G[COUT * NCOLS];
__device__ __align__(16) float g_tapw[TT * NCELL * 16];
__device__ __align__(16) int   g_tapi[TT * NCELL * 16];
__device__ int   g_win[TT * 2];

// ---------------------------------------------------------------------------
// Kernel P: merged convert_w + pack + taps
// ---------------------------------------------------------------------------
#define W4CNT ((COUT * CIN) / 4)
#define W4BLK ((W4CNT + 255) / 256)
#define PKCNT (CIN * NPAD)
#define PKBLK ((PKCNT + 255) / 256)

__global__ void prep_kernel(const float* __restrict__ W, const float* __restrict__ y,
                            const float* __restrict__ rois) {
    if (blockIdx.x < W4BLK) {
        int i = blockIdx.x * 256 + threadIdx.x;
        if (i >= W4CNT) return;
        float4 v = ((const float4*)W)[i];
        __half2* Wh2 = (__half2*)g_Wh;
        Wh2[i * 2 + 0] = __half2{__float2half_rn(v.x), __float2half_rn(v.y)};
        Wh2[i * 2 + 1] = __half2{__float2half_rn(v.z), __float2half_rn(v.w)};
    } else if (blockIdx.x < W4BLK + PKBLK) {
        int idx = (blockIdx.x - W4BLK) * 256 + threadIdx.x;
        if (idx >= PKCNT) return;
        int k = idx / NPAD;
        int n = idx - k * NPAD;
        float v = 0.0f;
        if (n < NCOLS) {
            int t = n / NCELL;
            int r = n - t * NCELL;
            int oy = r / NOUT;
            int ox = r - oy * NOUT;
            v = y[((k * TT + t) * HF + 2 * oy) * WF + 2 * ox];
        }
        __half h = __float2half_rn(v);
        g_Bh[idx] = h;
        g_Bl[idx] = __float2half_rn(v - __half2float(h));
    } else {
        const int t = blockIdx.x - (W4BLK + PKBLK);
        const int cell = threadIdx.x;
        if (cell >= NCELL) return;
        const float SC = 1.0f / 16.0f;
        float bx1 = rois[t * 4 + 0] * SC;
        float by1 = rois[t * 4 + 1] * SC;
        float bx2 = rois[t * 4 + 2] * SC;
        float by2 = rois[t * 4 + 3] * SC;
        float bw = fmaxf(bx2 - bx1, 1.0f) / (float)NOUT;
        float bh = fmaxf(by2 - by1, 1.0f) / (float)NOUT;

        if (cell == 0) {
            int sxi = (int)floorf(bx1);
            int syi = (int)floorf(by1);
            int exi = (int)ceilf(bx2);
            int eyi = (int)ceilf(by2);
            g_win[t * 2 + 0] = (syi + NOUT < HF) ? syi : (eyi - NOUT);
            g_win[t * 2 + 1] = (sxi + NOUT < HF) ? sxi : (exi - NOUT);
        }

        int oy = cell / NOUT;
        int ox = cell - oy * NOUT;
        float* tw = g_tapw + (t * NCELL + cell) * 16;
        int*   ti = g_tapi + (t * NCELL + cell) * 16;

#pragma unroll
        for (int s = 0; s < 2; s++) {
#pragma unroll
            for (int r = 0; r < 2; r++) {
                int base = (s * 2 + r) * 4;
                float py = by1 + ((float)oy + ((float)s + 0.5f) * 0.5f) * bh;
                float px = bx1 + ((float)ox + ((float)r + 0.5f) * 0.5f) * bw;
                bool oob = (py < -1.0f) | (py > (float)HF) | (px < -1.0f) | (px > (float)WF);
                if (oob) {
                    tw[base + 0] = 0.f; tw[base + 1] = 0.f; tw[base + 2] = 0.f; tw[base + 3] = 0.f;
                    ti[base + 0] = 0;   ti[base + 1] = 0;   ti[base + 2] = 0;   ti[base + 3] = 0;
                } else {
                    float yc = fminf(fmaxf(py, 0.0f), (float)(HF - 1));
                    float xc = fminf(fmaxf(px, 0.0f), (float)(WF - 1));
                    int y0 = (int)floorf(yc);
                    int x0 = (int)floorf(xc);
                    int y1i = min(y0 + 1, HF - 1);
                    int x1i = min(x0 + 1, WF - 1);
                    float ly = yc - (float)y0;
                    float lx = xc - (float)x0;
                    tw[base + 0] = 0.25f * (1.f - ly) * (1.f - lx);
                    tw[base + 1] = 0.25f * (1.f - ly) * lx;
                    tw[base + 2] = 0.25f * ly * (1.f - lx);
                    tw[base + 3] = 0.25f * ly * lx;
                    ti[base + 0] = y0 * WF + x0;
                    ti[base + 1] = y0 * WF + x1i;
                    ti[base + 2] = y1i * WF + x0;
                    ti[base + 3] = y1i * WF + x1i;
                }
            }
        }
    }
}

// ---------------------------------------------------------------------------
// Kernel 2: fp16 2-product tensor-core GEMM + bias + BN + exact GELU
// BM=128, BN=64, BK=32; 256 threads; ldmatrix; 3-stage cp.async
// Products: Wh*Bh + Wh*Bl (W unsplit; dropped Wlo*B term ~2^-12)
// ---------------------------------------------------------------------------
#define BM 128
#define BN 64
#define BK 32
#define KSTEPS (CIN / BK)     // 48
#define ASTR 40               // 80B rows
#define BSTR 72               // 144B rows

#define AH_OFF 0
#define BH_OFF (BM * ASTR)                  // 5120
#define BL_OFF (BH_OFF + BK * BSTR)         // 7424
#define STAGE_ELEMS (BL_OFF + BK * BSTR)    // 9728 halfs
#define NSTAGE 3
#define SMEM_BYTES (NSTAGE * STAGE_ELEMS * 2)  // 58368

__device__ __forceinline__ void cp16(void* smem, const void* gmem) {
    unsigned sa = (unsigned)__cvta_generic_to_shared(smem);
    asm volatile("cp.async.cg.shared.global [%0], [%1], 16;\n" :: "r"(sa), "l"(gmem));
}
__device__ __forceinline__ void ldsm4(unsigned* r, const void* p) {
    unsigned a = (unsigned)__cvta_generic_to_shared(p);
    asm volatile("ldmatrix.sync.aligned.m8n8.x4.shared.b16 {%0,%1,%2,%3}, [%4];\n"
        : "=r"(r[0]), "=r"(r[1]), "=r"(r[2]), "=r"(r[3]) : "r"(a));
}
__device__ __forceinline__ void ldsm4t(unsigned* r, const void* p) {
    unsigned a = (unsigned)__cvta_generic_to_shared(p);
    asm volatile("ldmatrix.sync.aligned.m8n8.x4.trans.shared.b16 {%0,%1,%2,%3}, [%4];\n"
        : "=r"(r[0]), "=r"(r[1]), "=r"(r[2]), "=r"(r[3]) : "r"(a));
}

#define MMA_F16(c, a, b0, b1)                                               \
    asm volatile(                                                           \
        "mma.sync.aligned.m16n8k16.row.col.f32.f16.f16.f32 "                \
        "{%0,%1,%2,%3}, {%4,%5,%6,%7}, {%8,%9}, {%0,%1,%2,%3};\n"           \
        : "+f"(c[0]), "+f"(c[1]), "+f"(c[2]), "+f"(c[3])                    \
        : "r"(a[0]), "r"(a[1]), "r"(a[2]), "r"(a[3]), "r"(b0), "r"(b1))

extern __shared__ __half smem_buf[];

__global__ void __launch_bounds__(256) gemm_bn_gelu_kernel(
    const float* __restrict__ bias,
    const float* __restrict__ gamma,
    const float* __restrict__ beta,
    const float* __restrict__ rmean,
    const float* __restrict__ rvar)
{
    const int tid = threadIdx.x;
    const int bm = blockIdx.y * BM;
    const int bn = blockIdx.x * BN;

    const int lane = tid & 31;
    const int warp = tid >> 5;
    const int wm = warp >> 1;
    const int wn = warp & 1;
    const int frow = lane >> 2;
    const int fcolp = (lane & 3) * 2;
    const int sel = lane >> 3;
    const int lr = lane & 7;

    float acc[2][4][4];
#pragma unroll
    for (int mt = 0; mt < 2; mt++)
#pragma unroll
        for (int nt = 0; nt < 4; nt++)
#pragma unroll
            for (int i = 0; i < 4; i++) acc[mt][nt][i] = 0.0f;

    auto prefetch = [&](int s, int k0) {
        __half* st = smem_buf + s * STAGE_ELEMS;
        // A: 128 rows x 32 k = 512 x 16B
#pragma unroll
        for (int i = tid; i < 512; i += 256) {
            int row = i >> 2;
            int u = i & 3;
            cp16(&st[AH_OFF + row * ASTR + u * 8],
                 &g_Wh[(size_t)(bm + row) * CIN + k0 + u * 8]);
        }
        // B hi/lo: 32 k-rows x 64 n each = 2 x 256 x 16B
#pragma unroll
        for (int i = tid; i < 512; i += 256) {
            int hsel = i >> 8;
            int idx = i & 255;
            int row = idx >> 3;
            int u = idx & 7;
            __half* dst = &st[(hsel ? BL_OFF : BH_OFF) + row * BSTR + u * 8];
            const __half* src = (hsel ? g_Bl : g_Bh) + (size_t)(k0 + row) * NPAD + bn + u * 8;
            cp16(dst, src);
        }
        asm volatile("cp.async.commit_group;\n");
    };

    auto consume = [&](int s) {
        const __half* st = smem_buf + s * STAGE_ELEMS;
        const unsigned short* sAh = (const unsigned short*)(st + AH_OFF);
        const unsigned short* sBh = (const unsigned short*)(st + BH_OFF);
        const unsigned short* sBl = (const unsigned short*)(st + BL_OFF);
#pragma unroll
        for (int h = 0; h < 2; h++) {
            const int kb = h * 16;
            unsigned ah[2][4], bh[2][4], bl[2][4];
            const int arow = (sel & 1) * 8 + lr;
            const int akof = (sel >> 1) * 8;
#pragma unroll
            for (int mt = 0; mt < 2; mt++) {
                int r = wm * 32 + mt * 16 + arow;
                ldsm4(ah[mt], &sAh[r * ASTR + kb + akof]);
            }
#pragma unroll
            for (int np = 0; np < 2; np++) {
                int kr = kb + (sel & 1) * 8 + lr;
                int nc = wn * 32 + np * 16 + (sel >> 1) * 8;
                ldsm4t(bh[np], &sBh[kr * BSTR + nc]);
                ldsm4t(bl[np], &sBl[kr * BSTR + nc]);
            }
#pragma unroll
            for (int np = 0; np < 2; np++)
#pragma unroll
                for (int q = 0; q < 2; q++) {
                    int nt = np * 2 + q;
#pragma unroll
                    for (int mt = 0; mt < 2; mt++) {
                        MMA_F16(acc[mt][nt], ah[mt], bh[np][q * 2], bh[np][q * 2 + 1]);
                        MMA_F16(acc[mt][nt], ah[mt], bl[np][q * 2], bl[np][q * 2 + 1]);
                    }
                }
        }
    };

    prefetch(0, 0);
    prefetch(1, BK);

    int s = 0;
    for (int ks = 0; ks < KSTEPS - 1; ks++) {
        asm volatile("cp.async.wait_group 1;\n");
        __syncthreads();
        if (ks + 2 < KSTEPS) prefetch((s + 2) % NSTAGE, (ks + 2) * BK);
        consume(s);
        s = (s + 1) % NSTAGE;
    }
    asm volatile("cp.async.wait_group 0;\n");
    __syncthreads();
    consume(s);

    // Epilogue: bias + BN + exact GELU
#pragma unroll
    for (int mt = 0; mt < 2; mt++) {
        int r0g = bm + wm * 32 + mt * 16 + frow;
#pragma unroll
        for (int half = 0; half < 2; half++) {
            int o = r0g + half * 8;
            float inv = gamma[o] * rsqrtf(rvar[o] + 1e-6f);
            float b0 = bias[o];
            float mu = rmean[o];
            float be = beta[o];
#pragma unroll
            for (int nt = 0; nt < 4; nt++) {
                int n = bn + wn * 32 + nt * 8 + fcolp;
                if (n < NCOLS) {
                    float v0 = acc[mt][nt][half * 2 + 0] + b0;
                    float v1 = acc[mt][nt][half * 2 + 1] + b0;
                    v0 = (v0 - mu) * inv + be;
                    v1 = (v1 - mu) * inv + be;
                    v0 = v0 * normcdff(v0);
                    v1 = v1 * normcdff(v1);
                    *(float2*)&g_G[(size_t)o * NCOLS + n] = make_float2(v0, v1);
                }
            }
        }
    }
}

// ---------------------------------------------------------------------------
// Kernel 3: ROI-align + place + residual, conflict-free gather
// 32 channels/block, 256 threads, grid (COUT/32, TT)
// ---------------------------------------------------------------------------
#define CH 32
#define TSTR 197

__global__ void __launch_bounds__(256) roi_place_kernel(
    const float* __restrict__ x_t,
    float* __restrict__ out)
{
    __shared__ __align__(16) float s_tw[NCELL * 16];
    __shared__ __align__(16) int   s_ti[NCELL * 16];
    __shared__ float ts[CH * TSTR];      // plane tiles, stride 197 (coprime 32)
    __shared__ float gsm[CH * NCELL];
    __shared__ float wsm[CH * NCELL];
    __shared__ int   s_mask[PLANE];

    const int t = blockIdx.y;
    const int c0 = blockIdx.x * CH;
    const int tid = threadIdx.x;

    {
        const float4* gw4 = (const float4*)(g_tapw + t * NCELL * 16);
        const int4*   gi4 = (const int4*)(g_tapi + t * NCELL * 16);
        for (int i = tid; i < NCELL * 4; i += 256) {
            ((float4*)s_tw)[i] = gw4[i];
            ((int4*)s_ti)[i] = gi4[i];
        }
    }
    if (tid < PLANE) {
        const int mt = g_win[t * 2 + 0];
        const int ml = g_win[t * 2 + 1];
        int h = tid / WF;
        int w = tid - h * WF;
        int oy = h - mt, ox = w - ml;
        s_mask[tid] = (oy >= 0 && oy < NOUT && ox >= 0 && ox < NOUT) ? oy * NOUT + ox : -1;
    }
    const float4* src4 = (const float4*)x_t;
    for (int i = tid; i < CH * 49; i += 256) {
        int c = i / 49, q = i - (i / 49) * 49;
        float4 v = src4[(size_t)((c0 + c) * TT + t) * 49 + q];
        float* dst = ts + c * TSTR + q * 4;
        dst[0] = v.x; dst[1] = v.y; dst[2] = v.z; dst[3] = v.w;
    }
    for (int i = tid; i < CH * NCELL; i += 256) {
        int p = i / NCELL, cell = i - (i / NCELL) * NCELL;
        gsm[p * NCELL + cell] = g_G[(size_t)(c0 + p) * NCOLS + t * NCELL + cell];
    }
    __syncthreads();

    // warp = one cell across 32 channels; 197 coprime 32 -> conflict-free
    for (int j = tid; j < NCELL * 32; j += 256) {
        int cell = j >> 5;
        int p = j & 31;
        const float* tp = ts + p * TSTR;
        const float4* tw4 = (const float4*)(s_tw + cell * 16);
        const int4*   ti4 = (const int4*)(s_ti + cell * 16);
        float mr = 0.0f;
#pragma unroll
        for (int g4 = 0; g4 < 4; g4++) {
            float4 w = tw4[g4];
            int4 ix = ti4[g4];
            mr = fmaf(w.x, tp[ix.x], mr);
            mr = fmaf(w.y, tp[ix.y], mr);
            mr = fmaf(w.z, tp[ix.z], mr);
            mr = fmaf(w.w, tp[ix.w], mr);
        }
        wsm[p * NCELL + cell] = gsm[p * NCELL + cell] * mr;
    }
    __syncthreads();

    float4* dst4 = (float4*)out;
    for (int i = tid; i < CH * 49; i += 256) {
        int c = i / 49, q = i - (i / 49) * 49;
        const float* tp = ts + c * TSTR + q * 4;
        float4 v = make_float4(tp[0], tp[1], tp[2], tp[3]);
        float* vp = (float*)&v;
        int e0 = q * 4;
#pragma unroll
        for (int j = 0; j < 4; j++) {
            int mi = s_mask[e0 + j];
            if (mi >= 0) vp[j] += wsm[c * NCELL + mi];
        }
        dst4[(size_t)((c0 + c) * TT + t) * 49 + q] = v;
    }
}

// ---------------------------------------------------------------------------
// Launch
// ---------------------------------------------------------------------------
extern "C" void kernel_launch(void* const* d_in, const int* in_sizes, int n_in,
                              void* d_out, int out_size) {
    const float* y      = (const float*)d_in[0];
    const float* x_t    = (const float*)d_in[1];
    const float* rois   = (const float*)d_in[2];
    const float* conv_w = (const float*)d_in[3];
    const float* conv_b = (const float*)d_in[4];
    const float* gamma  = (const float*)d_in[5];
    const float* beta   = (const float*)d_in[6];
    const float* rmean  = (const float*)d_in[7];
    const float* rvar   = (const float*)d_in[8];
    float* out = (float*)d_out;

    prep_kernel<<<W4BLK + PKBLK + TT, 256>>>(conv_w, y, rois);
    {
        cudaFuncSetAttribute(gemm_bn_gelu_kernel,
                             cudaFuncAttributeMaxDynamicSharedMemorySize, SMEM_BYTES);
        dim3 grid(NPAD / BN, COUT / BM);  // (13, 24)
        gemm_bn_gelu_kernel<<<grid, 256, SMEM_BYTES>>>(conv_b, gamma, beta, rmean, rvar);
    }
    {
        dim3 grid(COUT / CH, TT);
        roi_place_kernel<<<grid, 256>>>(x_t, out);
    }
}

// round 7
// speedup vs baseline: 3.3986x; 1.2206x over previous
#include <cuda_runtime.h>
#include <cuda_fp16.h>
#include <math.h>
#include <stdint.h>

// Problem constants
#define CIN   1536
#define COUT  3072
#define TT    16
#define HF    14
#define WF    14
#define NOUT  7
#define NCELL (NOUT * NOUT)        // 49
#define NCOLS (TT * NCELL)         // 784
#define NPAD  832                  // 13 * 64
#define PLANE (HF * WF)            // 196

// ---------------------------------------------------------------------------
// Device scratch
// ---------------------------------------------------------------------------
__device__ __align__(16) __half g_Wh[COUT * CIN];           // W fp16
__device__ __align__(16) __half g_Bh[CIN * NPAD];           // y fp16, k-major
__device__ __align__(16) float g_G[COUT * NCOLS];
__device__ __align__(16) float g_tapw[TT * NCELL * 16];
__device__ __align__(16) int   g_tapi[TT * NCELL * 16];
__device__ int   g_win[TT * 2];

// ---------------------------------------------------------------------------
// Kernel P: merged convert_w + pack + taps
// ---------------------------------------------------------------------------
#define W4CNT ((COUT * CIN) / 4)
#define W4BLK ((W4CNT + 255) / 256)
#define PKCNT (CIN * NPAD)
#define PKBLK ((PKCNT + 255) / 256)

__global__ void prep_kernel(const float* __restrict__ W, const float* __restrict__ y,
                            const float* __restrict__ rois) {
    if (blockIdx.x < W4BLK) {
        int i = blockIdx.x * 256 + threadIdx.x;
        if (i >= W4CNT) return;
        float4 v = ((const float4*)W)[i];
        __half2* Wh2 = (__half2*)g_Wh;
        Wh2[i * 2 + 0] = __half2{__float2half_rn(v.x), __float2half_rn(v.y)};
        Wh2[i * 2 + 1] = __half2{__float2half_rn(v.z), __float2half_rn(v.w)};
    } else if (blockIdx.x < W4BLK + PKBLK) {
        int idx = (blockIdx.x - W4BLK) * 256 + threadIdx.x;
        if (idx >= PKCNT) return;
        int k = idx / NPAD;
        int n = idx - k * NPAD;
        float v = 0.0f;
        if (n < NCOLS) {
            int t = n / NCELL;
            int r = n - t * NCELL;
            int oy = r / NOUT;
            int ox = r - oy * NOUT;
            v = y[((k * TT + t) * HF + 2 * oy) * WF + 2 * ox];
        }
        g_Bh[idx] = __float2half_rn(v);
    } else {
        const int t = blockIdx.x - (W4BLK + PKBLK);
        const int cell = threadIdx.x;
        if (cell >= NCELL) return;
        const float SC = 1.0f / 16.0f;
        float bx1 = rois[t * 4 + 0] * SC;
        float by1 = rois[t * 4 + 1] * SC;
        float bx2 = rois[t * 4 + 2] * SC;
        float by2 = rois[t * 4 + 3] * SC;
        float bw = fmaxf(bx2 - bx1, 1.0f) / (float)NOUT;
        float bh = fmaxf(by2 - by1, 1.0f) / (float)NOUT;

        if (cell == 0) {
            int sxi = (int)floorf(bx1);
            int syi = (int)floorf(by1);
            int exi = (int)ceilf(bx2);
            int eyi = (int)ceilf(by2);
            g_win[t * 2 + 0] = (syi + NOUT < HF) ? syi : (eyi - NOUT);
            g_win[t * 2 + 1] = (sxi + NOUT < HF) ? sxi : (exi - NOUT);
        }

        int oy = cell / NOUT;
        int ox = cell - oy * NOUT;
        float* tw = g_tapw + (t * NCELL + cell) * 16;
        int*   ti = g_tapi + (t * NCELL + cell) * 16;

#pragma unroll
        for (int s = 0; s < 2; s++) {
#pragma unroll
            for (int r = 0; r < 2; r++) {
                int base = (s * 2 + r) * 4;
                float py = by1 + ((float)oy + ((float)s + 0.5f) * 0.5f) * bh;
                float px = bx1 + ((float)ox + ((float)r + 0.5f) * 0.5f) * bw;
                bool oob = (py < -1.0f) | (py > (float)HF) | (px < -1.0f) | (px > (float)WF);
                if (oob) {
                    tw[base + 0] = 0.f; tw[base + 1] = 0.f; tw[base + 2] = 0.f; tw[base + 3] = 0.f;
                    ti[base + 0] = 0;   ti[base + 1] = 0;   ti[base + 2] = 0;   ti[base + 3] = 0;
                } else {
                    float yc = fminf(fmaxf(py, 0.0f), (float)(HF - 1));
                    float xc = fminf(fmaxf(px, 0.0f), (float)(WF - 1));
                    int y0 = (int)floorf(yc);
                    int x0 = (int)floorf(xc);
                    int y1i = min(y0 + 1, HF - 1);
                    int x1i = min(x0 + 1, WF - 1);
                    float ly = yc - (float)y0;
                    float lx = xc - (float)x0;
                    tw[base + 0] = 0.25f * (1.f - ly) * (1.f - lx);
                    tw[base + 1] = 0.25f * (1.f - ly) * lx;
                    tw[base + 2] = 0.25f * ly * (1.f - lx);
                    tw[base + 3] = 0.25f * ly * lx;
                    ti[base + 0] = y0 * WF + x0;
                    ti[base + 1] = y0 * WF + x1i;
                    ti[base + 2] = y1i * WF + x0;
                    ti[base + 3] = y1i * WF + x1i;
                }
            }
        }
    }
}

// ---------------------------------------------------------------------------
// Kernel 2: fp16 single-product tensor-core GEMM + bias + BN + exact GELU
// BM=128, BN=64, BK=32; 256 threads; ldmatrix; 3-stage cp.async
// ---------------------------------------------------------------------------
#define BM 128
#define BN 64
#define BK 32
#define KSTEPS (CIN / BK)     // 48
#define ASTR 40               // 80B rows
#define BSTR 72               // 144B rows

#define AH_OFF 0
#define BH_OFF (BM * ASTR)                  // 5120
#define STAGE_ELEMS (BH_OFF + BK * BSTR)    // 7424 halfs
#define NSTAGE 3
#define SMEM_BYTES (NSTAGE * STAGE_ELEMS * 2)  // 44544

__device__ __forceinline__ void cp16(void* smem, const void* gmem) {
    unsigned sa = (unsigned)__cvta_generic_to_shared(smem);
    asm volatile("cp.async.cg.shared.global [%0], [%1], 16;\n" :: "r"(sa), "l"(gmem));
}
__device__ __forceinline__ void ldsm4(unsigned* r, const void* p) {
    unsigned a = (unsigned)__cvta_generic_to_shared(p);
    asm volatile("ldmatrix.sync.aligned.m8n8.x4.shared.b16 {%0,%1,%2,%3}, [%4];\n"
        : "=r"(r[0]), "=r"(r[1]), "=r"(r[2]), "=r"(r[3]) : "r"(a));
}
__device__ __forceinline__ void ldsm4t(unsigned* r, const void* p) {
    unsigned a = (unsigned)__cvta_generic_to_shared(p);
    asm volatile("ldmatrix.sync.aligned.m8n8.x4.trans.shared.b16 {%0,%1,%2,%3}, [%4];\n"
        : "=r"(r[0]), "=r"(r[1]), "=r"(r[2]), "=r"(r[3]) : "r"(a));
}

#define MMA_F16(c, a, b0, b1)                                               \
    asm volatile(                                                           \
        "mma.sync.aligned.m16n8k16.row.col.f32.f16.f16.f32 "                \
        "{%0,%1,%2,%3}, {%4,%5,%6,%7}, {%8,%9}, {%0,%1,%2,%3};\n"           \
        : "+f"(c[0]), "+f"(c[1]), "+f"(c[2]), "+f"(c[3])                    \
        : "r"(a[0]), "r"(a[1]), "r"(a[2]), "r"(a[3]), "r"(b0), "r"(b1))

extern __shared__ __half smem_buf[];

__global__ void __launch_bounds__(256) gemm_bn_gelu_kernel(
    const float* __restrict__ bias,
    const float* __restrict__ gamma,
    const float* __restrict__ beta,
    const float* __restrict__ rmean,
    const float* __restrict__ rvar)
{
    const int tid = threadIdx.x;
    const int bm = blockIdx.y * BM;
    const int bn = blockIdx.x * BN;

    const int lane = tid & 31;
    const int warp = tid >> 5;
    const int wm = warp >> 1;
    const int wn = warp & 1;
    const int frow = lane >> 2;
    const int fcolp = (lane & 3) * 2;
    const int sel = lane >> 3;
    const int lr = lane & 7;

    float acc[2][4][4];
#pragma unroll
    for (int mt = 0; mt < 2; mt++)
#pragma unroll
        for (int nt = 0; nt < 4; nt++)
#pragma unroll
            for (int i = 0; i < 4; i++) acc[mt][nt][i] = 0.0f;

    auto prefetch = [&](int s, int k0) {
        __half* st = smem_buf + s * STAGE_ELEMS;
        // A: 128 rows x 32 k = 512 x 16B
#pragma unroll
        for (int i = tid; i < 512; i += 256) {
            int row = i >> 2;
            int u = i & 3;
            cp16(&st[AH_OFF + row * ASTR + u * 8],
                 &g_Wh[(size_t)(bm + row) * CIN + k0 + u * 8]);
        }
        // B: 32 k-rows x 64 n = 256 x 16B
        {
            int i = tid;
            if (i < 256) {
                int row = i >> 3;
                int u = i & 7;
                cp16(&st[BH_OFF + row * BSTR + u * 8],
                     &g_Bh[(size_t)(k0 + row) * NPAD + bn + u * 8]);
            }
        }
        asm volatile("cp.async.commit_group;\n");
    };

    auto consume = [&](int s) {
        const __half* st = smem_buf + s * STAGE_ELEMS;
        const unsigned short* sAh = (const unsigned short*)(st + AH_OFF);
        const unsigned short* sBh = (const unsigned short*)(st + BH_OFF);
#pragma unroll
        for (int h = 0; h < 2; h++) {
            const int kb = h * 16;
            unsigned ah[2][4], bh[2][4];
            const int arow = (sel & 1) * 8 + lr;
            const int akof = (sel >> 1) * 8;
#pragma unroll
            for (int mt = 0; mt < 2; mt++) {
                int r = wm * 32 + mt * 16 + arow;
                ldsm4(ah[mt], &sAh[r * ASTR + kb + akof]);
            }
#pragma unroll
            for (int np = 0; np < 2; np++) {
                int kr = kb + (sel & 1) * 8 + lr;
                int nc = wn * 32 + np * 16 + (sel >> 1) * 8;
                ldsm4t(bh[np], &sBh[kr * BSTR + nc]);
            }
#pragma unroll
            for (int np = 0; np < 2; np++)
#pragma unroll
                for (int q = 0; q < 2; q++) {
                    int nt = np * 2 + q;
#pragma unroll
                    for (int mt = 0; mt < 2; mt++)
                        MMA_F16(acc[mt][nt], ah[mt], bh[np][q * 2], bh[np][q * 2 + 1]);
                }
        }
    };

    prefetch(0, 0);
    prefetch(1, BK);

    int s = 0;
    for (int ks = 0; ks < KSTEPS - 1; ks++) {
        asm volatile("cp.async.wait_group 1;\n");
        __syncthreads();
        if (ks + 2 < KSTEPS) prefetch((s + 2) % NSTAGE, (ks + 2) * BK);
        consume(s);
        s = (s + 1) % NSTAGE;
    }
    asm volatile("cp.async.wait_group 0;\n");
    __syncthreads();
    consume(s);

    // Epilogue: bias + BN + exact GELU
#pragma unroll
    for (int mt = 0; mt < 2; mt++) {
        int r0g = bm + wm * 32 + mt * 16 + frow;
#pragma unroll
        for (int half = 0; half < 2; half++) {
            int o = r0g + half * 8;
            float inv = gamma[o] * rsqrtf(rvar[o] + 1e-6f);
            float b0 = bias[o];
            float mu = rmean[o];
            float be = beta[o];
#pragma unroll
            for (int nt = 0; nt < 4; nt++) {
                int n = bn + wn * 32 + nt * 8 + fcolp;
                if (n < NCOLS) {
                    float v0 = acc[mt][nt][half * 2 + 0] + b0;
                    float v1 = acc[mt][nt][half * 2 + 1] + b0;
                    v0 = (v0 - mu) * inv + be;
                    v1 = (v1 - mu) * inv + be;
                    v0 = v0 * normcdff(v0);
                    v1 = v1 * normcdff(v1);
                    *(float2*)&g_G[(size_t)o * NCOLS + n] = make_float2(v0, v1);
                }
            }
        }
    }
}

// ---------------------------------------------------------------------------
// Kernel 3: ROI-align + place + residual, conflict-free gather
// 32 channels/block, 256 threads, grid (COUT/32, TT)
// ---------------------------------------------------------------------------
#define CH 32
#define TSTR 197

__global__ void __launch_bounds__(256) roi_place_kernel(
    const float* __restrict__ x_t,
    float* __restrict__ out)
{
    __shared__ __align__(16) float s_tw[NCELL * 16];
    __shared__ __align__(16) int   s_ti[NCELL * 16];
    __shared__ float ts[CH * TSTR];      // plane tiles, stride 197 (coprime 32)
    __shared__ float gsm[CH * NCELL];
    __shared__ float wsm[CH * NCELL];
    __shared__ int   s_mask[PLANE];

    const int t = blockIdx.y;
    const int c0 = blockIdx.x * CH;
    const int tid = threadIdx.x;

    {
        const float4* gw4 = (const float4*)(g_tapw + t * NCELL * 16);
        const int4*   gi4 = (const int4*)(g_tapi + t * NCELL * 16);
        for (int i = tid; i < NCELL * 4; i += 256) {
            ((float4*)s_tw)[i] = gw4[i];
            ((int4*)s_ti)[i] = gi4[i];
        }
    }
    if (tid < PLANE) {
        const int mt = g_win[t * 2 + 0];
        const int ml = g_win[t * 2 + 1];
        int h = tid / WF;
        int w = tid - h * WF;
        int oy = h - mt, ox = w - ml;
        s_mask[tid] = (oy >= 0 && oy < NOUT && ox >= 0 && ox < NOUT) ? oy * NOUT + ox : -1;
    }
    const float4* src4 = (const float4*)x_t;
    for (int i = tid; i < CH * 49; i += 256) {
        int c = i / 49, q = i - (i / 49) * 49;
        float4 v = src4[(size_t)((c0 + c) * TT + t) * 49 + q];
        float* dst = ts + c * TSTR + q * 4;
        dst[0] = v.x; dst[1] = v.y; dst[2] = v.z; dst[3] = v.w;
    }
    for (int i = tid; i < CH * NCELL; i += 256) {
        int p = i / NCELL, cell = i - (i / NCELL) * NCELL;
        gsm[p * NCELL + cell] = g_G[(size_t)(c0 + p) * NCOLS + t * NCELL + cell];
    }
    __syncthreads();

    // warp = one cell across 32 channels; 197 coprime 32 -> conflict-free
    for (int j = tid; j < NCELL * 32; j += 256) {
        int cell = j >> 5;
        int p = j & 31;
        const float* tp = ts + p * TSTR;
        const float4* tw4 = (const float4*)(s_tw + cell * 16);
        const int4*   ti4 = (const int4*)(s_ti + cell * 16);
        float mr = 0.0f;
#pragma unroll
        for (int g4 = 0; g4 < 4; g4++) {
            float4 w = tw4[g4];
            int4 ix = ti4[g4];
            mr = fmaf(w.x, tp[ix.x], mr);
            mr = fmaf(w.y, tp[ix.y], mr);
            mr = fmaf(w.z, tp[ix.z], mr);
            mr = fmaf(w.w, tp[ix.w], mr);
        }
        wsm[p * NCELL + cell] = gsm[p * NCELL + cell] * mr;
    }
    __syncthreads();

    float4* dst4 = (float4*)out;
    for (int i = tid; i < CH * 49; i += 256) {
        int c = i / 49, q = i - (i / 49) * 49;
        const float* tp = ts + c * TSTR + q * 4;
        float4 v = make_float4(tp[0], tp[1], tp[2], tp[3]);
        float* vp = (float*)&v;
        int e0 = q * 4;
#pragma unroll
        for (int j = 0; j < 4; j++) {
            int mi = s_mask[e0 + j];
            if (mi >= 0) vp[j] += wsm[c * NCELL + mi];
        }
        dst4[(size_t)((c0 + c) * TT + t) * 49 + q] = v;
    }
}

// ---------------------------------------------------------------------------
// Launch
// ---------------------------------------------------------------------------
extern "C" void kernel_launch(void* const* d_in, const int* in_sizes, int n_in,
                              void* d_out, int out_size) {
    const float* y      = (const float*)d_in[0];
    const float* x_t    = (const float*)d_in[1];
    const float* rois   = (const float*)d_in[2];
    const float* conv_w = (const float*)d_in[3];
    const float* conv_b = (const float*)d_in[4];
    const float* gamma  = (const float*)d_in[5];
    const float* beta   = (const float*)d_in[6];
    const float* rmean  = (const float*)d_in[7];
    const float* rvar   = (const float*)d_in[8];
    float* out = (float*)d_out;

    prep_kernel<<<W4BLK + PKBLK + TT, 256>>>(conv_w, y, rois);
    {
        cudaFuncSetAttribute(gemm_bn_gelu_kernel,
                             cudaFuncAttributeMaxDynamicSharedMemorySize, SMEM_BYTES);
        dim3 grid(NPAD / BN, COUT / BM);  // (13, 24)
        gemm_bn_gelu_kernel<<<grid, 256, SMEM_BYTES>>>(conv_b, gamma, beta, rmean, rvar);
    }
    {
        dim3 grid(COUT / CH, TT);
        roi_place_kernel<<<grid, 256>>>(x_t, out);
    }
}

// round 8
// speedup vs baseline: 3.6245x; 1.0665x over previous
#include <cuda_runtime.h>
#include <cuda_fp16.h>
#include <math.h>
#include <stdint.h>

// Problem constants
#define CIN   1536
#define COUT  3072
#define TT    16
#define HF    14
#define WF    14
#define NOUT  7
#define NCELL (NOUT * NOUT)        // 49
#define NCOLS (TT * NCELL)         // 784
#define NPAD  832                  // 13 * 64
#define PLANE (HF * WF)            // 196

// ---------------------------------------------------------------------------
// Device scratch
// ---------------------------------------------------------------------------
__device__ __align__(16) __half g_Wh[COUT * CIN];           // W fp16
__device__ __align__(16) __half g_Bh[CIN * NPAD];           // y fp16, k-major
__device__ __align__(16) float g_G[COUT * NCOLS];
__device__ __align__(16) float g_tapw[TT * NCELL * 16];
__device__ __align__(16) int   g_tapi[TT * NCELL * 16];
__device__ int   g_win[TT * 2];

// ---------------------------------------------------------------------------
// Kernel P: merged convert_w + pack + taps
// ---------------------------------------------------------------------------
#define W4CNT ((COUT * CIN) / 4)
#define W4BLK ((W4CNT + 255) / 256)
#define PKCNT (CIN * NPAD)
#define PKBLK ((PKCNT + 255) / 256)

__global__ void prep_kernel(const float* __restrict__ W, const float* __restrict__ y,
                            const float* __restrict__ rois) {
    if (blockIdx.x < W4BLK) {
        int i = blockIdx.x * 256 + threadIdx.x;
        if (i >= W4CNT) return;
        float4 v = ((const float4*)W)[i];
        __half2* Wh2 = (__half2*)g_Wh;
        Wh2[i * 2 + 0] = __half2{__float2half_rn(v.x), __float2half_rn(v.y)};
        Wh2[i * 2 + 1] = __half2{__float2half_rn(v.z), __float2half_rn(v.w)};
    } else if (blockIdx.x < W4BLK + PKBLK) {
        int idx = (blockIdx.x - W4BLK) * 256 + threadIdx.x;
        if (idx >= PKCNT) return;
        int k = idx / NPAD;
        int n = idx - k * NPAD;
        float v = 0.0f;
        if (n < NCOLS) {
            int t = n / NCELL;
            int r = n - t * NCELL;
            int oy = r / NOUT;
            int ox = r - oy * NOUT;
            v = y[((k * TT + t) * HF + 2 * oy) * WF + 2 * ox];
        }
        g_Bh[idx] = __float2half_rn(v);
    } else {
        const int t = blockIdx.x - (W4BLK + PKBLK);
        const int cell = threadIdx.x;
        if (cell >= NCELL) return;
        const float SC = 1.0f / 16.0f;
        float bx1 = rois[t * 4 + 0] * SC;
        float by1 = rois[t * 4 + 1] * SC;
        float bx2 = rois[t * 4 + 2] * SC;
        float by2 = rois[t * 4 + 3] * SC;
        float bw = fmaxf(bx2 - bx1, 1.0f) / (float)NOUT;
        float bh = fmaxf(by2 - by1, 1.0f) / (float)NOUT;

        if (cell == 0) {
            int sxi = (int)floorf(bx1);
            int syi = (int)floorf(by1);
            int exi = (int)ceilf(bx2);
            int eyi = (int)ceilf(by2);
            g_win[t * 2 + 0] = (syi + NOUT < HF) ? syi : (eyi - NOUT);
            g_win[t * 2 + 1] = (sxi + NOUT < HF) ? sxi : (exi - NOUT);
        }

        int oy = cell / NOUT;
        int ox = cell - oy * NOUT;
        float* tw = g_tapw + (t * NCELL + cell) * 16;
        int*   ti = g_tapi + (t * NCELL + cell) * 16;

#pragma unroll
        for (int s = 0; s < 2; s++) {
#pragma unroll
            for (int r = 0; r < 2; r++) {
                int base = (s * 2 + r) * 4;
                float py = by1 + ((float)oy + ((float)s + 0.5f) * 0.5f) * bh;
                float px = bx1 + ((float)ox + ((float)r + 0.5f) * 0.5f) * bw;
                bool oob = (py < -1.0f) | (py > (float)HF) | (px < -1.0f) | (px > (float)WF);
                if (oob) {
                    tw[base + 0] = 0.f; tw[base + 1] = 0.f; tw[base + 2] = 0.f; tw[base + 3] = 0.f;
                    ti[base + 0] = 0;   ti[base + 1] = 0;   ti[base + 2] = 0;   ti[base + 3] = 0;
                } else {
                    float yc = fminf(fmaxf(py, 0.0f), (float)(HF - 1));
                    float xc = fminf(fmaxf(px, 0.0f), (float)(WF - 1));
                    int y0 = (int)floorf(yc);
                    int x0 = (int)floorf(xc);
                    int y1i = min(y0 + 1, HF - 1);
                    int x1i = min(x0 + 1, WF - 1);
                    float ly = yc - (float)y0;
                    float lx = xc - (float)x0;
                    tw[base + 0] = 0.25f * (1.f - ly) * (1.f - lx);
                    tw[base + 1] = 0.25f * (1.f - ly) * lx;
                    tw[base + 2] = 0.25f * ly * (1.f - lx);
                    tw[base + 3] = 0.25f * ly * lx;
                    ti[base + 0] = y0 * WF + x0;
                    ti[base + 1] = y0 * WF + x1i;
                    ti[base + 2] = y1i * WF + x0;
                    ti[base + 3] = y1i * WF + x1i;
                }
            }
        }
    }
}

// ---------------------------------------------------------------------------
// Kernel 2: fp16 tensor-core GEMM + bias + BN + exact GELU
// BM=64, BN=64, BK=32; 128 threads (4 warps, 2x2); 4-stage cp.async depth-3
// ---------------------------------------------------------------------------
#define BM 64
#define BN 64
#define BK 32
#define KSTEPS (CIN / BK)     // 48
#define ASTR 40               // 80B rows
#define BSTR 72               // 144B rows

#define AH_OFF 0
#define BH_OFF (BM * ASTR)                  // 2560
#define STAGE_ELEMS (BH_OFF + BK * BSTR)    // 4864 halfs = 9728B
#define NSTAGE 4
#define SMEM_BYTES (NSTAGE * STAGE_ELEMS * 2)  // 38912

__device__ __forceinline__ void cp16(void* smem, const void* gmem) {
    unsigned sa = (unsigned)__cvta_generic_to_shared(smem);
    asm volatile("cp.async.cg.shared.global [%0], [%1], 16;\n" :: "r"(sa), "l"(gmem));
}
__device__ __forceinline__ void ldsm4(unsigned* r, const void* p) {
    unsigned a = (unsigned)__cvta_generic_to_shared(p);
    asm volatile("ldmatrix.sync.aligned.m8n8.x4.shared.b16 {%0,%1,%2,%3}, [%4];\n"
        : "=r"(r[0]), "=r"(r[1]), "=r"(r[2]), "=r"(r[3]) : "r"(a));
}
__device__ __forceinline__ void ldsm4t(unsigned* r, const void* p) {
    unsigned a = (unsigned)__cvta_generic_to_shared(p);
    asm volatile("ldmatrix.sync.aligned.m8n8.x4.trans.shared.b16 {%0,%1,%2,%3}, [%4];\n"
        : "=r"(r[0]), "=r"(r[1]), "=r"(r[2]), "=r"(r[3]) : "r"(a));
}

#define MMA_F16(c, a, b0, b1)                                               \
    asm volatile(                                                           \
        "mma.sync.aligned.m16n8k16.row.col.f32.f16.f16.f32 "                \
        "{%0,%1,%2,%3}, {%4,%5,%6,%7}, {%8,%9}, {%0,%1,%2,%3};\n"           \
        : "+f"(c[0]), "+f"(c[1]), "+f"(c[2]), "+f"(c[3])                    \
        : "r"(a[0]), "r"(a[1]), "r"(a[2]), "r"(a[3]), "r"(b0), "r"(b1))

extern __shared__ __half smem_buf[];

__global__ void __launch_bounds__(128) gemm_bn_gelu_kernel(
    const float* __restrict__ bias,
    const float* __restrict__ gamma,
    const float* __restrict__ beta,
    const float* __restrict__ rmean,
    const float* __restrict__ rvar)
{
    const int tid = threadIdx.x;
    const int bm = blockIdx.y * BM;
    const int bn = blockIdx.x * BN;

    const int lane = tid & 31;
    const int warp = tid >> 5;
    const int wm = warp >> 1;       // 0..1
    const int wn = warp & 1;        // 0..1
    const int frow = lane >> 2;
    const int fcolp = (lane & 3) * 2;
    const int sel = lane >> 3;
    const int lr = lane & 7;

    float acc[2][4][4];
#pragma unroll
    for (int mt = 0; mt < 2; mt++)
#pragma unroll
        for (int nt = 0; nt < 4; nt++)
#pragma unroll
            for (int i = 0; i < 4; i++) acc[mt][nt][i] = 0.0f;

    // Prefetch mappings: A = 64 rows x 4 chunks (256 total), B = 32 rows x 8 chunks (256)
    const int a_row0 = tid >> 1;              // chunks 0..127: rows 0..63, u = (tid&1)*? -> need 4 u per row
    // chunk id c in [0,256): row = c>>2, u = c&3; threads cover c = tid and tid+128
    auto prefetch = [&](int s, int k0) {
        __half* st = smem_buf + s * STAGE_ELEMS;
#pragma unroll
        for (int c = tid; c < 256; c += 128) {
            int row = c >> 2;
            int u = c & 3;
            cp16(&st[AH_OFF + row * ASTR + u * 8],
                 &g_Wh[(size_t)(bm + row) * CIN + k0 + u * 8]);
        }
#pragma unroll
        for (int c = tid; c < 256; c += 128) {
            int row = c >> 3;
            int u = c & 7;
            cp16(&st[BH_OFF + row * BSTR + u * 8],
                 &g_Bh[(size_t)(k0 + row) * NPAD + bn + u * 8]);
        }
        asm volatile("cp.async.commit_group;\n");
    };

    auto consume = [&](int s) {
        const __half* st = smem_buf + s * STAGE_ELEMS;
        const unsigned short* sAh = (const unsigned short*)(st + AH_OFF);
        const unsigned short* sBh = (const unsigned short*)(st + BH_OFF);
#pragma unroll
        for (int h = 0; h < 2; h++) {
            const int kb = h * 16;
            unsigned ah[2][4], bh[2][4];
            const int arow = (sel & 1) * 8 + lr;
            const int akof = (sel >> 1) * 8;
#pragma unroll
            for (int mt = 0; mt < 2; mt++) {
                int r = wm * 32 + mt * 16 + arow;
                ldsm4(ah[mt], &sAh[r * ASTR + kb + akof]);
            }
#pragma unroll
            for (int np = 0; np < 2; np++) {
                int kr = kb + (sel & 1) * 8 + lr;
                int nc = wn * 32 + np * 16 + (sel >> 1) * 8;
                ldsm4t(bh[np], &sBh[kr * BSTR + nc]);
            }
#pragma unroll
            for (int np = 0; np < 2; np++)
#pragma unroll
                for (int q = 0; q < 2; q++) {
                    int nt = np * 2 + q;
#pragma unroll
                    for (int mt = 0; mt < 2; mt++)
                        MMA_F16(acc[mt][nt], ah[mt], bh[np][q * 2], bh[np][q * 2 + 1]);
                }
        }
    };

    prefetch(0, 0);
    prefetch(1, BK);
    prefetch(2, 2 * BK);

    for (int ks = 0; ks < KSTEPS; ks++) {
        int rem = KSTEPS - 1 - ks;   // prefetches still outstanding after this stage's
        if (rem >= 2)      asm volatile("cp.async.wait_group 2;\n");
        else if (rem == 1) asm volatile("cp.async.wait_group 1;\n");
        else               asm volatile("cp.async.wait_group 0;\n");
        __syncthreads();
        if (ks + 3 < KSTEPS) prefetch((ks + 3) & 3, (ks + 3) * BK);
        consume(ks & 3);
    }

    // Epilogue: bias + BN + exact GELU
#pragma unroll
    for (int mt = 0; mt < 2; mt++) {
        int r0g = bm + wm * 32 + mt * 16 + frow;
#pragma unroll
        for (int half = 0; half < 2; half++) {
            int o = r0g + half * 8;
            float inv = gamma[o] * rsqrtf(rvar[o] + 1e-6f);
            float b0 = bias[o];
            float mu = rmean[o];
            float be = beta[o];
#pragma unroll
            for (int nt = 0; nt < 4; nt++) {
                int n = bn + wn * 32 + nt * 8 + fcolp;
                if (n < NCOLS) {
                    float v0 = acc[mt][nt][half * 2 + 0] + b0;
                    float v1 = acc[mt][nt][half * 2 + 1] + b0;
                    v0 = (v0 - mu) * inv + be;
                    v1 = (v1 - mu) * inv + be;
                    v0 = v0 * normcdff(v0);
                    v1 = v1 * normcdff(v1);
                    *(float2*)&g_G[(size_t)o * NCOLS + n] = make_float2(v0, v1);
                }
            }
        }
    }
}

// ---------------------------------------------------------------------------
// Kernel 3: ROI-align + place + residual, conflict-free gather
// 32 channels/block, 256 threads, grid (COUT/32, TT)
// ---------------------------------------------------------------------------
#define CH 32
#define TSTR 197

__global__ void __launch_bounds__(256) roi_place_kernel(
    const float* __restrict__ x_t,
    float* __restrict__ out)
{
    __shared__ __align__(16) float s_tw[NCELL * 16];
    __shared__ __align__(16) int   s_ti[NCELL * 16];
    __shared__ float ts[CH * TSTR];      // plane tiles, stride 197 (coprime 32)
    __shared__ float gsm[CH * NCELL];
    __shared__ float wsm[CH * NCELL];
    __shared__ int   s_mask[PLANE];

    const int t = blockIdx.y;
    const int c0 = blockIdx.x * CH;
    const int tid = threadIdx.x;

    {
        const float4* gw4 = (const float4*)(g_tapw + t * NCELL * 16);
        const int4*   gi4 = (const int4*)(g_tapi + t * NCELL * 16);
        for (int i = tid; i < NCELL * 4; i += 256) {
            ((float4*)s_tw)[i] = gw4[i];
            ((int4*)s_ti)[i] = gi4[i];
        }
    }
    if (tid < PLANE) {
        const int mt = g_win[t * 2 + 0];
        const int ml = g_win[t * 2 + 1];
        int h = tid / WF;
        int w = tid - h * WF;
        int oy = h - mt, ox = w - ml;
        s_mask[tid] = (oy >= 0 && oy < NOUT && ox >= 0 && ox < NOUT) ? oy * NOUT + ox : -1;
    }
    const float4* src4 = (const float4*)x_t;
    for (int i = tid; i < CH * 49; i += 256) {
        int c = i / 49, q = i - (i / 49) * 49;
        float4 v = src4[(size_t)((c0 + c) * TT + t) * 49 + q];
        float* dst = ts + c * TSTR + q * 4;
        dst[0] = v.x; dst[1] = v.y; dst[2] = v.z; dst[3] = v.w;
    }
    for (int i = tid; i < CH * NCELL; i += 256) {
        int p = i / NCELL, cell = i - (i / NCELL) * NCELL;
        gsm[p * NCELL + cell] = g_G[(size_t)(c0 + p) * NCOLS + t * NCELL + cell];
    }
    __syncthreads();

    // warp = one cell across 32 channels; 197 coprime 32 -> conflict-free
    for (int j = tid; j < NCELL * 32; j += 256) {
        int cell = j >> 5;
        int p = j & 31;
        const float* tp = ts + p * TSTR;
        const float4* tw4 = (const float4*)(s_tw + cell * 16);
        const int4*   ti4 = (const int4*)(s_ti + cell * 16);
        float mr = 0.0f;
#pragma unroll
        for (int g4 = 0; g4 < 4; g4++) {
            float4 w = tw4[g4];
            int4 ix = ti4[g4];
            mr = fmaf(w.x, tp[ix.x], mr);
            mr = fmaf(w.y, tp[ix.y], mr);
            mr = fmaf(w.z, tp[ix.z], mr);
            mr = fmaf(w.w, tp[ix.w], mr);
        }
        wsm[p * NCELL + cell] = gsm[p * NCELL + cell] * mr;
    }
    __syncthreads();

    float4* dst4 = (float4*)out;
    for (int i = tid; i < CH * 49; i += 256) {
        int c = i / 49, q = i - (i / 49) * 49;
        const float* tp = ts + c * TSTR + q * 4;
        float4 v = make_float4(tp[0], tp[1], tp[2], tp[3]);
        float* vp = (float*)&v;
        int e0 = q * 4;
#pragma unroll
        for (int j = 0; j < 4; j++) {
            int mi = s_mask[e0 + j];
            if (mi >= 0) vp[j] += wsm[c * NCELL + mi];
        }
        dst4[(size_t)((c0 + c) * TT + t) * 49 + q] = v;
    }
}

// ---------------------------------------------------------------------------
// Launch
// ---------------------------------------------------------------------------
extern "C" void kernel_launch(void* const* d_in, const int* in_sizes, int n_in,
                              void* d_out, int out_size) {
    const float* y      = (const float*)d_in[0];
    const float* x_t    = (const float*)d_in[1];
    const float* rois   = (const float*)d_in[2];
    const float* conv_w = (const float*)d_in[3];
    const float* conv_b = (const float*)d_in[4];
    const float* gamma  = (const float*)d_in[5];
    const float* beta   = (const float*)d_in[6];
    const float* rmean  = (const float*)d_in[7];
    const float* rvar   = (const float*)d_in[8];
    float* out = (float*)d_out;

    prep_kernel<<<W4BLK + PKBLK + TT, 256>>>(conv_w, y, rois);
    {
        cudaFuncSetAttribute(gemm_bn_gelu_kernel,
                             cudaFuncAttributeMaxDynamicSharedMemorySize, SMEM_BYTES);
        dim3 grid(NPAD / BN, COUT / BM);  // (13, 48) = 624 CTAs
        gemm_bn_gelu_kernel<<<grid, 128, SMEM_BYTES>>>(conv_b, gamma, beta, rmean, rvar);
    }
    {
        dim3 grid(COUT / CH, TT);
        roi_place_kernel<<<grid, 256>>>(x_t, out);
    }
}